// round 1
// baseline (speedup 1.0000x reference)
#include <cuda_runtime.h>
#include <cuda_bf16.h>

// Problem constants (fixed shapes for SAE_57105885168101)
#define B_SZ   16384
#define D_SZ   256
#define H_SZ   8192
#define K_TOP  32

// Encoder GEMM tiling
#define BM 128
#define BN 128
#define BK 16
#define NTHREADS 256

// ---------------------------------------------------------------------------
// Scratch (static device globals — no allocation allowed)
// ---------------------------------------------------------------------------
__device__ float g_tkval[B_SZ * K_TOP];     // per-row top-k values
__device__ int   g_tkidx[B_SZ * K_TOP];     // per-row top-k indices
__device__ int   g_counts[H_SZ];            // integer latent counts
__device__ float g_colsum[64 * D_SZ];       // per-block column sums of x
__device__ float g_qpart[64];               // per-block sum of x^2
__device__ float g_e2part[B_SZ / 8];        // per-decode-block sum of e^2

// ---------------------------------------------------------------------------
// Kernel 1: column statistics of x (for total_variance) + zero counts
// grid 64, 256 threads. Block g owns rows [g*256, g*256+256), thread t = col t.
// ---------------------------------------------------------------------------
__global__ __launch_bounds__(256) void colstat_kernel(const float* __restrict__ x)
{
    __shared__ float red[256];
    int g = blockIdx.x, t = threadIdx.x;

    int gid = g * 256 + t;
    if (gid < H_SZ) g_counts[gid] = 0;

    const float* xb = x + (size_t)(g * 256) * D_SZ;
    float s = 0.f, q = 0.f;
    #pragma unroll 8
    for (int r = 0; r < 256; r++) {
        float v = xb[r * D_SZ + t];   // coalesced across threads
        s += v;
        q += v * v;
    }
    g_colsum[g * D_SZ + t] = s;

    red[t] = q;
    __syncthreads();
    for (int sft = 128; sft > 0; sft >>= 1) {
        if (t < sft) red[t] += red[t + sft];
        __syncthreads();
    }
    if (t == 0) g_qpart[g] = red[0];
}

// ---------------------------------------------------------------------------
// Kernel 2: fused encoder GEMM + bias + ReLU + streaming per-row top-32
// grid = B/BM = 128 blocks, 256 threads, dynamic SMEM.
// pre_acts tile never touches HBM.
// ---------------------------------------------------------------------------
__global__ __launch_bounds__(256, 1) void encode_topk_kernel(
    const float* __restrict__ x,
    const float* __restrict__ W_enc,
    const float* __restrict__ b_enc,
    const float* __restrict__ b_dec)
{
    extern __shared__ float sm[];
    float* As    = sm;                         // [BK][BM+4]  (k-major, padded)
    float* Bs    = As + BK * (BM + 4);         // [BK][BN+4]
    float* acts  = Bs + BK * (BN + 4);         // [BM][BN+1]  (129 stride: conflict-free row scan)
    float* tkv   = acts + BM * (BN + 1);       // [BM][33]
    int*   tki   = (int*)(tkv + BM * 33);      // [BM][33]
    float* tkmin = (float*)(tki + BM * 33);    // [BM]
    int*   tkpos = (int*)(tkmin + BM);         // [BM]

    const int t  = threadIdx.x;
    const int r0 = blockIdx.x * BM;

    // init per-row top-k state
    if (t < BM) {
        #pragma unroll
        for (int j = 0; j < K_TOP; j++) {
            tkv[t * 33 + j] = -1e30f;
            tki[t * 33 + j] = j;
        }
        tkmin[t] = -1e30f;
        tkpos[t] = 0;
    }

    const int trow = t >> 4, tcol = t & 15;
    const int m0 = trow * 8, n0 = tcol * 8;

    for (int h0 = 0; h0 < H_SZ; h0 += BN) {
        float acc[8][8];
        #pragma unroll
        for (int i = 0; i < 8; i++)
            #pragma unroll
            for (int j = 0; j < 8; j++) acc[i][j] = 0.f;

        for (int kb = 0; kb < D_SZ; kb += BK) {
            __syncthreads();   // also guards acts/top-k of previous chunk
            // stage A tile (sae_in = x - b_dec), k-major
            #pragma unroll
            for (int i = 0; i < 2; i++) {
                int q = t + 256 * i;
                int row = q >> 2, seg = q & 3;
                float4 v  = *(const float4*)(x + (size_t)(r0 + row) * D_SZ + kb + seg * 4);
                float4 bd = *(const float4*)(b_dec + kb + seg * 4);
                As[(seg * 4 + 0) * (BM + 4) + row] = v.x - bd.x;
                As[(seg * 4 + 1) * (BM + 4) + row] = v.y - bd.y;
                As[(seg * 4 + 2) * (BM + 4) + row] = v.z - bd.z;
                As[(seg * 4 + 3) * (BM + 4) + row] = v.w - bd.w;
            }
            // stage B tile (W_enc rows h0..h0+127), k-major
            #pragma unroll
            for (int i = 0; i < 2; i++) {
                int q = t + 256 * i;
                int row = q >> 2, seg = q & 3;
                float4 v = *(const float4*)(W_enc + (size_t)(h0 + row) * D_SZ + kb + seg * 4);
                Bs[(seg * 4 + 0) * (BN + 4) + row] = v.x;
                Bs[(seg * 4 + 1) * (BN + 4) + row] = v.y;
                Bs[(seg * 4 + 2) * (BN + 4) + row] = v.z;
                Bs[(seg * 4 + 3) * (BN + 4) + row] = v.w;
            }
            __syncthreads();

            #pragma unroll
            for (int k = 0; k < BK; k++) {
                float a[8], b[8];
                *(float4*)(a)     = *(const float4*)&As[k * (BM + 4) + m0];
                *(float4*)(a + 4) = *(const float4*)&As[k * (BM + 4) + m0 + 4];
                *(float4*)(b)     = *(const float4*)&Bs[k * (BN + 4) + n0];
                *(float4*)(b + 4) = *(const float4*)&Bs[k * (BN + 4) + n0 + 4];
                #pragma unroll
                for (int i = 0; i < 8; i++)
                    #pragma unroll
                    for (int j = 0; j < 8; j++)
                        acc[i][j] += a[i] * b[j];
            }
        }

        // bias + relu -> acts tile
        float be[8];
        #pragma unroll
        for (int j = 0; j < 8; j++) be[j] = __ldg(&b_enc[h0 + n0 + j]);
        #pragma unroll
        for (int i = 0; i < 8; i++)
            #pragma unroll
            for (int j = 0; j < 8; j++)
                acts[(m0 + i) * (BN + 1) + (n0 + j)] = fmaxf(acc[i][j] + be[j], 0.f);
        __syncthreads();

        // streaming top-k update: one thread per row
        if (t < BM) {
            float curmin = tkmin[t];
            int   pos    = tkpos[t];
            const float* arow = acts + t * (BN + 1);
            for (int c = 0; c < BN; c++) {
                float v = arow[c];
                if (v > curmin) {
                    tkv[t * 33 + pos] = v;
                    tki[t * 33 + pos] = h0 + c;
                    // rescan for new min
                    curmin = tkv[t * 33];
                    pos = 0;
                    #pragma unroll
                    for (int j = 1; j < K_TOP; j++) {
                        float u = tkv[t * 33 + j];
                        if (u < curmin) { curmin = u; pos = j; }
                    }
                }
            }
            tkmin[t] = curmin;
            tkpos[t] = pos;
        }
        // next chunk's first __syncthreads() orders acts reuse
    }
    __syncthreads();

    // dump per-row top-k lists to global
    for (int q = t; q < BM * K_TOP; q += NTHREADS) {
        int m = q >> 5, j = q & 31;
        int row = r0 + m;
        g_tkval[row * K_TOP + j] = tkv[m * 33 + j];
        g_tkidx[row * K_TOP + j] = tki[m * 33 + j];
    }
}

// ---------------------------------------------------------------------------
// Kernel 3: sparse decode + counts + e^2 partials
// grid = B/8 blocks, 256 threads. Thread t = output column t; 8 rows/block.
// ---------------------------------------------------------------------------
__global__ __launch_bounds__(256) void decode_kernel(
    const float* __restrict__ x,
    const float* __restrict__ W_dec,
    const float* __restrict__ b_dec,
    float* __restrict__ out)
{
    __shared__ float sval[8][K_TOP];
    __shared__ int   sidx[8][K_TOP];
    __shared__ float red[256];

    int blk = blockIdx.x;
    int r0  = blk * 8;
    int t   = threadIdx.x;

    // 256 threads load the 8x32 (idx,val) pairs + count atomics (integer => deterministic)
    {
        int r = t >> 5, j = t & 31;
        int row = r0 + r;
        float v = g_tkval[row * K_TOP + j];
        int  id = g_tkidx[row * K_TOP + j];
        sval[r][j] = v;
        sidx[r][j] = id;
        atomicAdd(&g_counts[id], 1);
    }
    __syncthreads();

    float bd = b_dec[t];
    float esum = 0.f;
    #pragma unroll
    for (int r = 0; r < 8; r++) {
        float acc = bd;
        #pragma unroll
        for (int j = 0; j < K_TOP; j++) {
            acc += sval[r][j] * __ldg(&W_dec[(size_t)sidx[r][j] * D_SZ + t]);
        }
        int row = r0 + r;
        out[(size_t)row * D_SZ + t] = acc;
        float e = acc - x[(size_t)row * D_SZ + t];
        esum += e * e;
    }

    red[t] = esum;
    __syncthreads();
    for (int s = 128; s > 0; s >>= 1) {
        if (t < s) red[t] += red[t + s];
        __syncthreads();
    }
    if (t == 0) g_e2part[blk] = red[0];
}

// ---------------------------------------------------------------------------
// Kernel 4: finalize — fvu scalar + counts -> float output
// 1 block, 256 threads. All reductions fixed-order (deterministic).
// ---------------------------------------------------------------------------
__global__ __launch_bounds__(256) void finalize_kernel(float* __restrict__ out)
{
    __shared__ float red[256];
    __shared__ float sh_var, sh_q, sh_e2;
    int t = threadIdx.x;

    // sum over blocks of column sums -> S_d; variance term S_d^2/B
    float S = 0.f;
    for (int g = 0; g < 64; g++) S += g_colsum[g * D_SZ + t];
    float term = S * S * (1.0f / (float)B_SZ);
    red[t] = term;
    __syncthreads();
    for (int s = 128; s > 0; s >>= 1) { if (t < s) red[t] += red[t + s]; __syncthreads(); }
    if (t == 0) sh_var = red[0];
    __syncthreads();

    // Q = sum x^2
    float qv = (t < 64) ? g_qpart[t] : 0.f;
    red[t] = qv;
    __syncthreads();
    for (int s = 128; s > 0; s >>= 1) { if (t < s) red[t] += red[t + s]; __syncthreads(); }
    if (t == 0) sh_q = red[0];
    __syncthreads();

    // sum e^2
    float e2 = 0.f;
    for (int i = t; i < B_SZ / 8; i += 256) e2 += g_e2part[i];
    red[t] = e2;
    __syncthreads();
    for (int s = 128; s > 0; s >>= 1) { if (t < s) red[t] += red[t + s]; __syncthreads(); }
    if (t == 0) sh_e2 = red[0];
    __syncthreads();

    if (t == 0) {
        float total_var = sh_q - sh_var;   // sum((x - mean)^2) via identity
        out[(size_t)B_SZ * D_SZ + H_SZ] = sh_e2 / total_var;
    }
    // counts (int -> float)
    for (int i = t; i < H_SZ; i += 256)
        out[(size_t)B_SZ * D_SZ + i] = (float)g_counts[i];
}

// ---------------------------------------------------------------------------
// Launch
// ---------------------------------------------------------------------------
extern "C" void kernel_launch(void* const* d_in, const int* in_sizes, int n_in,
                              void* d_out, int out_size)
{
    const float* x     = (const float*)d_in[0];
    const float* W_enc = (const float*)d_in[1];
    const float* b_enc = (const float*)d_in[2];
    const float* W_dec = (const float*)d_in[3];
    const float* b_dec = (const float*)d_in[4];
    // d_in[5] = k (always 32 for this problem)
    float* out = (float*)d_out;

    // dynamic SMEM for fused encode: As+Bs+acts+topk state
    const int smem_floats = BK * (BM + 4) + BK * (BN + 4)
                          + BM * (BN + 1)
                          + BM * 33 + BM * 33 + BM + BM;
    const int smem_bytes = smem_floats * 4;
    cudaFuncSetAttribute(encode_topk_kernel,
                         cudaFuncAttributeMaxDynamicSharedMemorySize, smem_bytes);

    colstat_kernel<<<64, 256>>>(x);
    encode_topk_kernel<<<B_SZ / BM, NTHREADS, smem_bytes>>>(x, W_enc, b_enc, b_dec);
    decode_kernel<<<B_SZ / 8, 256>>>(x, W_dec, b_dec, out);
    finalize_kernel<<<1, 256>>>(out);
}

// round 4
// speedup vs baseline: 1.3249x; 1.3249x over previous
#include <cuda_runtime.h>
#include <cuda_bf16.h>
#include <cstdint>

#define B_SZ   16384
#define D_SZ   256
#define H_SZ   8192
#define K_TOP  32
#define CAND_K   96     // superset size selected per row (exact bf16 top-96)
#define CAND_MAX 128    // candidate buffer cap

// ---------------------------------------------------------------------------
// Scratch (__device__ globals — no dynamic allocation allowed)
// ---------------------------------------------------------------------------
__device__ __nv_bfloat16 g_xb [B_SZ * D_SZ];                 // bf16(x - b_dec)
__device__ __nv_bfloat16 g_web[H_SZ * D_SZ];                 // bf16(W_enc)
__device__ __nv_bfloat16 g_acts[(size_t)B_SZ * H_SZ];        // bf16 relu(pre_acts)
__device__ int   g_cand[B_SZ * CAND_MAX];
__device__ int   g_ccnt[B_SZ];
__device__ float g_tkval[B_SZ * K_TOP];
__device__ int   g_tkidx[B_SZ * K_TOP];
__device__ int   g_counts[H_SZ];
__device__ float g_colsum[64 * D_SZ];
__device__ float g_qpart[64];
__device__ float g_e2part[B_SZ / 8];

// ---------------------------------------------------------------------------
// Helpers
// ---------------------------------------------------------------------------
__device__ __forceinline__ uint32_t smem_u32(const void* p) {
    uint32_t a;
    asm("{ .reg .u64 t; cvta.to.shared.u64 t, %1; cvt.u32.u64 %0, t; }" : "=r"(a) : "l"(p));
    return a;
}
#define CP_ASYNC16(dst, src) \
    asm volatile("cp.async.cg.shared.global [%0], [%1], 16;" :: "r"(dst), "l"(src))
#define CP_COMMIT() asm volatile("cp.async.commit_group;")
#define CP_WAIT(n)  asm volatile("cp.async.wait_group %0;" :: "n"(n))

__device__ __forceinline__ void ldsm_x4(uint32_t& r0, uint32_t& r1, uint32_t& r2, uint32_t& r3,
                                        uint32_t addr) {
    asm volatile("ldmatrix.sync.aligned.m8n8.x4.shared.b16 {%0,%1,%2,%3}, [%4];"
                 : "=r"(r0), "=r"(r1), "=r"(r2), "=r"(r3) : "r"(addr));
}
__device__ __forceinline__ void mma_16816(float* c, uint32_t a0, uint32_t a1, uint32_t a2,
                                          uint32_t a3, uint32_t b0, uint32_t b1) {
    asm volatile(
        "mma.sync.aligned.m16n8k16.row.col.f32.bf16.bf16.f32 "
        "{%0,%1,%2,%3}, {%4,%5,%6,%7}, {%8,%9}, {%0,%1,%2,%3};"
        : "+f"(c[0]), "+f"(c[1]), "+f"(c[2]), "+f"(c[3])
        : "r"(a0), "r"(a1), "r"(a2), "r"(a3), "r"(b0), "r"(b1));
}

// ---------------------------------------------------------------------------
// Kernel 0: convert x -> bf16(x - b_dec), W_enc -> bf16
// ---------------------------------------------------------------------------
__global__ __launch_bounds__(256) void conv_kernel(
    const float* __restrict__ x, const float* __restrict__ W_enc,
    const float* __restrict__ b_dec)
{
    int b = blockIdx.x, t = threadIdx.x;
    if (b < 2048) {
        size_t e0 = ((size_t)b * 256 + t) * 8;
        int col = (int)(e0 & (D_SZ - 1));
        float4 v0 = *(const float4*)(x + e0);
        float4 v1 = *(const float4*)(x + e0 + 4);
        float4 d0 = *(const float4*)(b_dec + col);
        float4 d1 = *(const float4*)(b_dec + col + 4);
        __nv_bfloat16 o[8];
        o[0]=__float2bfloat16_rn(v0.x-d0.x); o[1]=__float2bfloat16_rn(v0.y-d0.y);
        o[2]=__float2bfloat16_rn(v0.z-d0.z); o[3]=__float2bfloat16_rn(v0.w-d0.w);
        o[4]=__float2bfloat16_rn(v1.x-d1.x); o[5]=__float2bfloat16_rn(v1.y-d1.y);
        o[6]=__float2bfloat16_rn(v1.z-d1.z); o[7]=__float2bfloat16_rn(v1.w-d1.w);
        *(uint4*)(g_xb + e0) = *(uint4*)o;
    } else {
        size_t e0 = ((size_t)(b - 2048) * 256 + t) * 8;
        float4 v0 = *(const float4*)(W_enc + e0);
        float4 v1 = *(const float4*)(W_enc + e0 + 4);
        __nv_bfloat16 o[8];
        o[0]=__float2bfloat16_rn(v0.x); o[1]=__float2bfloat16_rn(v0.y);
        o[2]=__float2bfloat16_rn(v0.z); o[3]=__float2bfloat16_rn(v0.w);
        o[4]=__float2bfloat16_rn(v1.x); o[5]=__float2bfloat16_rn(v1.y);
        o[6]=__float2bfloat16_rn(v1.z); o[7]=__float2bfloat16_rn(v1.w);
        *(uint4*)(g_web + e0) = *(uint4*)o;
    }
}

// ---------------------------------------------------------------------------
// Kernel 1: column stats of x + zero counts
// ---------------------------------------------------------------------------
__global__ __launch_bounds__(256) void colstat_kernel(const float* __restrict__ x)
{
    __shared__ float red[256];
    int g = blockIdx.x, t = threadIdx.x;
    int gid = g * 256 + t;
    if (gid < H_SZ) g_counts[gid] = 0;
    const float* xb = x + (size_t)(g * 256) * D_SZ;
    float s = 0.f, q = 0.f;
    #pragma unroll 8
    for (int r = 0; r < 256; r++) {
        float v = xb[r * D_SZ + t];
        s += v; q += v * v;
    }
    g_colsum[g * D_SZ + t] = s;
    red[t] = q; __syncthreads();
    for (int sft = 128; sft > 0; sft >>= 1) { if (t < sft) red[t] += red[t + sft]; __syncthreads(); }
    if (t == 0) g_qpart[g] = red[0];
}

// ---------------------------------------------------------------------------
// Kernel 2: encoder GEMM via mma.sync (bf16 HMMA), 128x128x256 per block
// 8 warps (2x4 of 64x32 warp tiles), cp.async 2-stage over K halves.
// ---------------------------------------------------------------------------
#define KC       128
#define PITCH    136
#define STG_A    (128 * PITCH * 2)
#define OFF_A0   0
#define OFF_A1   STG_A
#define OFF_B0   (2 * STG_A)
#define OFF_B1   (3 * STG_A)
#define OFF_BES  (4 * STG_A)
#define ESM_TOTAL (OFF_BES + 512)
#define STAGE_PITCH_U32 68

__global__ __launch_bounds__(256, 1) void encode_kernel(const float* __restrict__ b_enc)
{
    extern __shared__ char smem[];
    const uint32_t sbase = smem_u32(smem);
    const int t = threadIdx.x;
    const int wid = t >> 5, lane = t & 31;
    const int h0 = blockIdx.x * 128;
    const int r0 = blockIdx.y * 128;

    const int wm = wid >> 2, wn = wid & 3;
    const int m0w = wm * 64, n0w = wn * 32;

    const char* gA = (const char*)(g_xb  + (size_t)r0 * D_SZ);
    const char* gB = (const char*)(g_web + (size_t)h0 * D_SZ);
    #pragma unroll
    for (int s = 0; s < 2; s++) {
        #pragma unroll
        for (int i = 0; i < 8; i++) {
            int idx = t + 256 * i;
            int row = idx >> 4, q = idx & 15;
            uint32_t dOff = (uint32_t)((row * PITCH + q * 8) * 2);
            size_t gOff = ((size_t)row * D_SZ + s * KC + q * 8) * 2;
            CP_ASYNC16(sbase + (s ? OFF_A1 : OFF_A0) + dOff, gA + gOff);
            CP_ASYNC16(sbase + (s ? OFF_B1 : OFF_B0) + dOff, gB + gOff);
        }
        CP_COMMIT();
    }
    ((float*)(smem + OFF_BES))[t & 127] = b_enc[h0 + (t & 127)];

    float acc[16][4];
    #pragma unroll
    for (int f = 0; f < 16; f++)
        #pragma unroll
        for (int e = 0; e < 4; e++) acc[f][e] = 0.f;

    const int aRow = lane & 15;
    const int aCol = (lane >> 4) << 3;
    const int bRow = ((lane >> 4) << 3) + (lane & 7);
    const int bCol = ((lane >> 3) & 1) << 3;

    CP_WAIT(1);
    __syncthreads();

    #pragma unroll
    for (int s = 0; s < 2; s++) {
        const uint32_t aBase = sbase + (s ? OFF_A1 : OFF_A0)
                             + ((m0w + aRow) * PITCH + aCol) * 2;
        const uint32_t bBase = sbase + (s ? OFF_B1 : OFF_B0)
                             + ((n0w + bRow) * PITCH + bCol) * 2;
        #pragma unroll
        for (int k0 = 0; k0 < KC; k0 += 16) {
            uint32_t a[4][4], b[2][4];
            #pragma unroll
            for (int i = 0; i < 4; i++)
                ldsm_x4(a[i][0], a[i][1], a[i][2], a[i][3],
                        aBase + (i * 16 * PITCH + k0) * 2);
            #pragma unroll
            for (int jp = 0; jp < 2; jp++)
                ldsm_x4(b[jp][0], b[jp][1], b[jp][2], b[jp][3],
                        bBase + (jp * 16 * PITCH + k0) * 2);
            #pragma unroll
            for (int i = 0; i < 4; i++)
                #pragma unroll
                for (int j = 0; j < 4; j++)
                    mma_16816(acc[i * 4 + j], a[i][0], a[i][1], a[i][2], a[i][3],
                              b[j >> 1][(j & 1) * 2], b[j >> 1][(j & 1) * 2 + 1]);
        }
        if (s == 0) {
            CP_WAIT(0);
            __syncthreads();
        }
    }
    __syncthreads();

    uint32_t* stg = (uint32_t*)smem;
    const float* bes = (const float*)(smem + OFF_BES);
    const int qr = lane >> 2, qc = lane & 3;
    #pragma unroll
    for (int i = 0; i < 4; i++) {
        #pragma unroll
        for (int j = 0; j < 4; j++) {
            int col = n0w + j * 8 + qc * 2;
            float b0 = bes[col], b1 = bes[col + 1];
            const float* c = acc[i * 4 + j];
            int mA = m0w + i * 16 + qr;
            float v0 = fmaxf(c[0] + b0, 0.f), v1 = fmaxf(c[1] + b1, 0.f);
            float v2 = fmaxf(c[2] + b0, 0.f), v3 = fmaxf(c[3] + b1, 0.f);
            uint32_t p0 = (uint32_t)__bfloat16_as_ushort(__float2bfloat16_rn(v0))
                        | ((uint32_t)__bfloat16_as_ushort(__float2bfloat16_rn(v1)) << 16);
            uint32_t p1 = (uint32_t)__bfloat16_as_ushort(__float2bfloat16_rn(v2))
                        | ((uint32_t)__bfloat16_as_ushort(__float2bfloat16_rn(v3)) << 16);
            stg[mA * STAGE_PITCH_U32 + (col >> 1)] = p0;
            stg[(mA + 8) * STAGE_PITCH_U32 + (col >> 1)] = p1;
        }
    }
    __syncthreads();
    #pragma unroll
    for (int i = 0; i < 8; i++) {
        int idx = t + 256 * i;
        int row = idx >> 4, q = idx & 15;
        uint4 v = *(const uint4*)((const char*)stg + row * (STAGE_PITCH_U32 * 4) + q * 16);
        *(uint4*)((char*)g_acts + ((size_t)(r0 + row) * H_SZ + h0) * 2 + q * 16) = v;
    }
}

// ---------------------------------------------------------------------------
// Kernel 3: exact per-row top-96 superset of bf16 acts (2-level radix select)
// ---------------------------------------------------------------------------
__global__ __launch_bounds__(256) void topk_kernel()
{
    __shared__ int hist[256];
    __shared__ int s_b, s_chi, s_T, s_cnt;
    const int row = blockIdx.x, t = threadIdx.x;

    const uint4* arow = (const uint4*)((const char*)g_acts + (size_t)row * H_SZ * 2);
    uint4 q[4];
    #pragma unroll
    for (int i = 0; i < 4; i++) q[i] = arow[t + 256 * i];

    hist[t] = 0;
    if (t == 0) s_cnt = 0;
    __syncthreads();

    #pragma unroll
    for (int i = 0; i < 4; i++) {
        const uint32_t* w = (const uint32_t*)&q[i];
        #pragma unroll
        for (int e = 0; e < 4; e++) {
            uint32_t u0 = w[e] & 0xFFFFu, u1 = w[e] >> 16;
            if (u0) atomicAdd(&hist[u0 >> 7], 1);
            if (u1) atomicAdd(&hist[u1 >> 7], 1);
        }
    }
    __syncthreads();
    if (t == 0) {
        int cum = 0, b = 255;
        for (; b >= 0; b--) {
            int nc = cum + hist[b];
            if (nc >= CAND_K) break;
            cum = nc;
        }
        s_b = (b < 0) ? 0 : b;
        s_chi = cum;
    }
    __syncthreads();
    const int bstar = s_b, chi = s_chi;
    if (t < 128) hist[t] = 0;
    __syncthreads();

    #pragma unroll
    for (int i = 0; i < 4; i++) {
        const uint32_t* w = (const uint32_t*)&q[i];
        #pragma unroll
        for (int e = 0; e < 4; e++) {
            uint32_t u0 = w[e] & 0xFFFFu, u1 = w[e] >> 16;
            if (u0 && (int)(u0 >> 7) == bstar) atomicAdd(&hist[u0 & 127], 1);
            if (u1 && (int)(u1 >> 7) == bstar) atomicAdd(&hist[u1 & 127], 1);
        }
    }
    __syncthreads();
    if (t == 0) {
        int cum = chi, s = 127;
        for (; s >= 0; s--) {
            cum += hist[s];
            if (cum >= CAND_K) break;
        }
        if (s < 0) s = 0;
        int T = (bstar << 7) | s;
        s_T = (T < 1) ? 1 : T;
    }
    __syncthreads();
    const uint32_t T = (uint32_t)s_T;

    #pragma unroll
    for (int i = 0; i < 4; i++) {
        const uint32_t* w = (const uint32_t*)&q[i];
        int cbase = (t + 256 * i) * 8;
        #pragma unroll
        for (int e = 0; e < 4; e++) {
            uint32_t u0 = w[e] & 0xFFFFu, u1 = w[e] >> 16;
            if (u0 >= T) {
                int p = atomicAdd(&s_cnt, 1);
                if (p < CAND_MAX) g_cand[row * CAND_MAX + p] = cbase + e * 2;
            }
            if (u1 >= T) {
                int p = atomicAdd(&s_cnt, 1);
                if (p < CAND_MAX) g_cand[row * CAND_MAX + p] = cbase + e * 2 + 1;
            }
        }
    }
    __syncthreads();
    if (t == 0) g_ccnt[row] = (s_cnt < CAND_MAX) ? s_cnt : CAND_MAX;
}

// ---------------------------------------------------------------------------
// Kernel 4: exact fp32 rescore — ONE THREAD per candidate, sequential-k FMA
// chain (identical arithmetic to the R1 kernel that passed at 2.3e-7).
// ---------------------------------------------------------------------------
__global__ __launch_bounds__(256) void rescore_kernel(
    const float* __restrict__ x, const float* __restrict__ W_enc,
    const float* __restrict__ b_enc, const float* __restrict__ b_dec)
{
    __shared__ float xs[D_SZ];
    __shared__ float cv[CAND_MAX];
    __shared__ int   ci[CAND_MAX];
    const int row = blockIdx.x, t = threadIdx.x;

    xs[t] = x[(size_t)row * D_SZ + t] - b_dec[t];
    const int cnt = g_ccnt[row];
    __syncthreads();

    if (t < cnt) {
        int idx = g_cand[row * CAND_MAX + t];
        const float* w = W_enc + (size_t)idx * D_SZ;
        float s = 0.f;
        #pragma unroll 8
        for (int k = 0; k < D_SZ; k++) s = fmaf(xs[k], __ldg(&w[k]), s);
        cv[t] = fmaxf(s + b_enc[idx], 0.f);
        ci[t] = idx;
    }
    __syncthreads();

    if (t < cnt) {
        float v = cv[t]; int id = ci[t];
        int rank = 0;
        for (int j = 0; j < cnt; j++) {
            float vo = cv[j];
            rank += (vo > v) || (vo == v && ci[j] < id);
        }
        if (rank < K_TOP) {
            g_tkval[row * K_TOP + rank] = v;
            g_tkidx[row * K_TOP + rank] = id;
        }
    }
}

// ---------------------------------------------------------------------------
// Kernel 5: sparse decode + counts + e^2 partials
// ---------------------------------------------------------------------------
__global__ __launch_bounds__(256) void decode_kernel(
    const float* __restrict__ x, const float* __restrict__ W_dec,
    const float* __restrict__ b_dec, float* __restrict__ out)
{
    __shared__ float sval[8][K_TOP];
    __shared__ int   sidx[8][K_TOP];
    __shared__ float red[256];
    int blk = blockIdx.x, r0 = blk * 8, t = threadIdx.x;
    {
        int r = t >> 5, j = t & 31;
        int row = r0 + r;
        sval[r][j] = g_tkval[row * K_TOP + j];
        int id = g_tkidx[row * K_TOP + j];
        sidx[r][j] = id;
        atomicAdd(&g_counts[id], 1);
    }
    __syncthreads();
    float bd = b_dec[t];
    float esum = 0.f;
    #pragma unroll
    for (int r = 0; r < 8; r++) {
        float acc = bd;
        #pragma unroll
        for (int j = 0; j < K_TOP; j++)
            acc += sval[r][j] * __ldg(&W_dec[(size_t)sidx[r][j] * D_SZ + t]);
        int row = r0 + r;
        out[(size_t)row * D_SZ + t] = acc;
        float e = acc - x[(size_t)row * D_SZ + t];
        esum += e * e;
    }
    red[t] = esum; __syncthreads();
    for (int s = 128; s > 0; s >>= 1) { if (t < s) red[t] += red[t + s]; __syncthreads(); }
    if (t == 0) g_e2part[blk] = red[0];
}

// ---------------------------------------------------------------------------
// Kernel 6: finalize
// ---------------------------------------------------------------------------
__global__ __launch_bounds__(256) void finalize_kernel(float* __restrict__ out)
{
    __shared__ float red[256];
    __shared__ float sh_var, sh_q, sh_e2;
    int t = threadIdx.x;
    float S = 0.f;
    for (int g = 0; g < 64; g++) S += g_colsum[g * D_SZ + t];
    red[t] = S * S * (1.0f / (float)B_SZ);
    __syncthreads();
    for (int s = 128; s > 0; s >>= 1) { if (t < s) red[t] += red[t + s]; __syncthreads(); }
    if (t == 0) sh_var = red[0];
    __syncthreads();
    red[t] = (t < 64) ? g_qpart[t] : 0.f;
    __syncthreads();
    for (int s = 128; s > 0; s >>= 1) { if (t < s) red[t] += red[t + s]; __syncthreads(); }
    if (t == 0) sh_q = red[0];
    __syncthreads();
    float e2 = 0.f;
    for (int i = t; i < B_SZ / 8; i += 256) e2 += g_e2part[i];
    red[t] = e2; __syncthreads();
    for (int s = 128; s > 0; s >>= 1) { if (t < s) red[t] += red[t + s]; __syncthreads(); }
    if (t == 0) sh_e2 = red[0];
    __syncthreads();
    if (t == 0) {
        float total_var = sh_q - sh_var;
        out[(size_t)B_SZ * D_SZ + H_SZ] = sh_e2 / total_var;
    }
    for (int i = t; i < H_SZ; i += 256)
        out[(size_t)B_SZ * D_SZ + i] = (float)g_counts[i];
}

// ---------------------------------------------------------------------------
// Launch
// ---------------------------------------------------------------------------
extern "C" void kernel_launch(void* const* d_in, const int* in_sizes, int n_in,
                              void* d_out, int out_size)
{
    const float* x     = (const float*)d_in[0];
    const float* W_enc = (const float*)d_in[1];
    const float* b_enc = (const float*)d_in[2];
    const float* W_dec = (const float*)d_in[3];
    const float* b_dec = (const float*)d_in[4];
    float* out = (float*)d_out;

    cudaFuncSetAttribute(encode_kernel,
                         cudaFuncAttributeMaxDynamicSharedMemorySize, ESM_TOTAL);

    conv_kernel<<<3072, 256>>>(x, W_enc, b_dec);
    colstat_kernel<<<64, 256>>>(x);
    encode_kernel<<<dim3(H_SZ / 128, B_SZ / 128), 256, ESM_TOTAL>>>(b_enc);
    topk_kernel<<<B_SZ, 256>>>();
    rescore_kernel<<<B_SZ, 256>>>(x, W_enc, b_enc, b_dec);
    decode_kernel<<<B_SZ / 8, 256>>>(x, W_dec, b_dec, out);
    finalize_kernel<<<1, 256>>>(out);
}

// round 5
// speedup vs baseline: 2.4756x; 1.8684x over previous
#include <cuda_runtime.h>
#include <cuda_fp16.h>
#include <cstdint>

#define B_SZ   16384
#define D_SZ   256
#define H_SZ   8192
#define K_TOP  32
#define CAND_K   64     // exact fp16 top-64 superset per row
#define CAND_MAX 96     // candidate buffer cap (tie headroom)
#define ROWG   4096     // row-group size (acts slab 64MB -> L2 resident)
#define NGRP   (B_SZ / ROWG)

// ---------------------------------------------------------------------------
// Scratch (__device__ globals)
// ---------------------------------------------------------------------------
__device__ __half g_xh [B_SZ * D_SZ];                 // fp16(x - b_dec)
__device__ __half g_weh[H_SZ * D_SZ];                 // fp16(W_enc)
__device__ __half g_acts[(size_t)B_SZ * H_SZ];        // fp16 relu(pre_acts)
__device__ int   g_cand[B_SZ * CAND_MAX];
__device__ int   g_ccnt[B_SZ];
__device__ float g_tkval[B_SZ * K_TOP];
__device__ int   g_tkidx[B_SZ * K_TOP];
__device__ int   g_counts[H_SZ];
__device__ float g_colsum[64 * D_SZ];
__device__ float g_qpart[64];
__device__ float g_e2part[B_SZ / 8];

// ---------------------------------------------------------------------------
// Helpers
// ---------------------------------------------------------------------------
__device__ __forceinline__ uint32_t smem_u32(const void* p) {
    uint32_t a;
    asm("{ .reg .u64 t; cvta.to.shared.u64 t, %1; cvt.u32.u64 %0, t; }" : "=r"(a) : "l"(p));
    return a;
}
#define CP_ASYNC16(dst, src) \
    asm volatile("cp.async.cg.shared.global [%0], [%1], 16;" :: "r"(dst), "l"(src))
#define CP_COMMIT() asm volatile("cp.async.commit_group;")
#define CP_WAIT(n)  asm volatile("cp.async.wait_group %0;" :: "n"(n))

__device__ __forceinline__ void ldsm_x4(uint32_t& r0, uint32_t& r1, uint32_t& r2, uint32_t& r3,
                                        uint32_t addr) {
    asm volatile("ldmatrix.sync.aligned.m8n8.x4.shared.b16 {%0,%1,%2,%3}, [%4];"
                 : "=r"(r0), "=r"(r1), "=r"(r2), "=r"(r3) : "r"(addr));
}
__device__ __forceinline__ void mma_16816(float* c, uint32_t a0, uint32_t a1, uint32_t a2,
                                          uint32_t a3, uint32_t b0, uint32_t b1) {
    asm volatile(
        "mma.sync.aligned.m16n8k16.row.col.f32.f16.f16.f32 "
        "{%0,%1,%2,%3}, {%4,%5,%6,%7}, {%8,%9}, {%0,%1,%2,%3};"
        : "+f"(c[0]), "+f"(c[1]), "+f"(c[2]), "+f"(c[3])
        : "r"(a0), "r"(a1), "r"(a2), "r"(a3), "r"(b0), "r"(b1));
}

// ---------------------------------------------------------------------------
// Kernel 0: convert x -> fp16(x - b_dec), W_enc -> fp16
// ---------------------------------------------------------------------------
__global__ __launch_bounds__(256) void conv_kernel(
    const float* __restrict__ x, const float* __restrict__ W_enc,
    const float* __restrict__ b_dec)
{
    int b = blockIdx.x, t = threadIdx.x;
    if (b < 2048) {
        size_t e0 = ((size_t)b * 256 + t) * 8;
        int col = (int)(e0 & (D_SZ - 1));
        float4 v0 = *(const float4*)(x + e0);
        float4 v1 = *(const float4*)(x + e0 + 4);
        float4 d0 = *(const float4*)(b_dec + col);
        float4 d1 = *(const float4*)(b_dec + col + 4);
        __half o[8];
        o[0]=__float2half_rn(v0.x-d0.x); o[1]=__float2half_rn(v0.y-d0.y);
        o[2]=__float2half_rn(v0.z-d0.z); o[3]=__float2half_rn(v0.w-d0.w);
        o[4]=__float2half_rn(v1.x-d1.x); o[5]=__float2half_rn(v1.y-d1.y);
        o[6]=__float2half_rn(v1.z-d1.z); o[7]=__float2half_rn(v1.w-d1.w);
        *(uint4*)(g_xh + e0) = *(uint4*)o;
    } else {
        size_t e0 = ((size_t)(b - 2048) * 256 + t) * 8;
        float4 v0 = *(const float4*)(W_enc + e0);
        float4 v1 = *(const float4*)(W_enc + e0 + 4);
        __half o[8];
        o[0]=__float2half_rn(v0.x); o[1]=__float2half_rn(v0.y);
        o[2]=__float2half_rn(v0.z); o[3]=__float2half_rn(v0.w);
        o[4]=__float2half_rn(v1.x); o[5]=__float2half_rn(v1.y);
        o[6]=__float2half_rn(v1.z); o[7]=__float2half_rn(v1.w);
        *(uint4*)(g_weh + e0) = *(uint4*)o;
    }
}

// ---------------------------------------------------------------------------
// Kernel 1: column stats of x + zero counts
// ---------------------------------------------------------------------------
__global__ __launch_bounds__(256) void colstat_kernel(const float* __restrict__ x)
{
    __shared__ float red[256];
    int g = blockIdx.x, t = threadIdx.x;
    int gid = g * 256 + t;
    if (gid < H_SZ) g_counts[gid] = 0;
    const float* xb = x + (size_t)(g * 256) * D_SZ;
    float s = 0.f, q = 0.f;
    #pragma unroll 8
    for (int r = 0; r < 256; r++) {
        float v = xb[r * D_SZ + t];
        s += v; q += v * v;
    }
    g_colsum[g * D_SZ + t] = s;
    red[t] = q; __syncthreads();
    for (int sft = 128; sft > 0; sft >>= 1) { if (t < sft) red[t] += red[t + sft]; __syncthreads(); }
    if (t == 0) g_qpart[g] = red[0];
}

// ---------------------------------------------------------------------------
// Kernel 2: encoder GEMM via mma.sync (fp16 HMMA), 128x128x256 per block
// ---------------------------------------------------------------------------
#define KC       128
#define PITCH    136
#define STG_A    (128 * PITCH * 2)
#define OFF_A0   0
#define OFF_A1   STG_A
#define OFF_B0   (2 * STG_A)
#define OFF_B1   (3 * STG_A)
#define OFF_BES  (4 * STG_A)
#define ESM_TOTAL (OFF_BES + 512)
#define STAGE_PITCH_U32 68

__global__ __launch_bounds__(256, 1) void encode_kernel(const float* __restrict__ b_enc,
                                                        int rgBase)
{
    extern __shared__ char smem[];
    const uint32_t sbase = smem_u32(smem);
    const int t = threadIdx.x;
    const int wid = t >> 5, lane = t & 31;
    const int h0 = blockIdx.x * 128;
    const int r0 = rgBase + blockIdx.y * 128;

    const int wm = wid >> 2, wn = wid & 3;
    const int m0w = wm * 64, n0w = wn * 32;

    const char* gA = (const char*)(g_xh  + (size_t)r0 * D_SZ);
    const char* gB = (const char*)(g_weh + (size_t)h0 * D_SZ);
    #pragma unroll
    for (int s = 0; s < 2; s++) {
        #pragma unroll
        for (int i = 0; i < 8; i++) {
            int idx = t + 256 * i;
            int row = idx >> 4, q = idx & 15;
            uint32_t dOff = (uint32_t)((row * PITCH + q * 8) * 2);
            size_t gOff = ((size_t)row * D_SZ + s * KC + q * 8) * 2;
            CP_ASYNC16(sbase + (s ? OFF_A1 : OFF_A0) + dOff, gA + gOff);
            CP_ASYNC16(sbase + (s ? OFF_B1 : OFF_B0) + dOff, gB + gOff);
        }
        CP_COMMIT();
    }
    ((float*)(smem + OFF_BES))[t & 127] = b_enc[h0 + (t & 127)];

    float acc[16][4];
    #pragma unroll
    for (int f = 0; f < 16; f++)
        #pragma unroll
        for (int e = 0; e < 4; e++) acc[f][e] = 0.f;

    const int aRow = lane & 15;
    const int aCol = (lane >> 4) << 3;
    const int bRow = ((lane >> 4) << 3) + (lane & 7);
    const int bCol = ((lane >> 3) & 1) << 3;

    CP_WAIT(1);
    __syncthreads();

    #pragma unroll
    for (int s = 0; s < 2; s++) {
        const uint32_t aBase = sbase + (s ? OFF_A1 : OFF_A0)
                             + ((m0w + aRow) * PITCH + aCol) * 2;
        const uint32_t bBase = sbase + (s ? OFF_B1 : OFF_B0)
                             + ((n0w + bRow) * PITCH + bCol) * 2;
        #pragma unroll
        for (int k0 = 0; k0 < KC; k0 += 16) {
            uint32_t a[4][4], b[2][4];
            #pragma unroll
            for (int i = 0; i < 4; i++)
                ldsm_x4(a[i][0], a[i][1], a[i][2], a[i][3],
                        aBase + (i * 16 * PITCH + k0) * 2);
            #pragma unroll
            for (int jp = 0; jp < 2; jp++)
                ldsm_x4(b[jp][0], b[jp][1], b[jp][2], b[jp][3],
                        bBase + (jp * 16 * PITCH + k0) * 2);
            #pragma unroll
            for (int i = 0; i < 4; i++)
                #pragma unroll
                for (int j = 0; j < 4; j++)
                    mma_16816(acc[i * 4 + j], a[i][0], a[i][1], a[i][2], a[i][3],
                              b[j >> 1][(j & 1) * 2], b[j >> 1][(j & 1) * 2 + 1]);
        }
        if (s == 0) {
            CP_WAIT(0);
            __syncthreads();
        }
    }
    __syncthreads();

    uint32_t* stg = (uint32_t*)smem;
    const float* bes = (const float*)(smem + OFF_BES);
    const int qr = lane >> 2, qc = lane & 3;
    #pragma unroll
    for (int i = 0; i < 4; i++) {
        #pragma unroll
        for (int j = 0; j < 4; j++) {
            int col = n0w + j * 8 + qc * 2;
            float b0 = bes[col], b1 = bes[col + 1];
            const float* c = acc[i * 4 + j];
            int mA = m0w + i * 16 + qr;
            float v0 = fmaxf(c[0] + b0, 0.f), v1 = fmaxf(c[1] + b1, 0.f);
            float v2 = fmaxf(c[2] + b0, 0.f), v3 = fmaxf(c[3] + b1, 0.f);
            uint32_t p0 = (uint32_t)__half_as_ushort(__float2half_rn(v0))
                        | ((uint32_t)__half_as_ushort(__float2half_rn(v1)) << 16);
            uint32_t p1 = (uint32_t)__half_as_ushort(__float2half_rn(v2))
                        | ((uint32_t)__half_as_ushort(__float2half_rn(v3)) << 16);
            stg[mA * STAGE_PITCH_U32 + (col >> 1)] = p0;
            stg[(mA + 8) * STAGE_PITCH_U32 + (col >> 1)] = p1;
        }
    }
    __syncthreads();
    #pragma unroll
    for (int i = 0; i < 8; i++) {
        int idx = t + 256 * i;
        int row = idx >> 4, q = idx & 15;
        uint4 v = *(const uint4*)((const char*)stg + row * (STAGE_PITCH_U32 * 4) + q * 16);
        *(uint4*)((char*)g_acts + ((size_t)(r0 + row) * H_SZ + h0) * 2 + q * 16) = v;
    }
}

// ---------------------------------------------------------------------------
// Kernel 3: exact per-row top-64 superset — register binary search, NO atomics
// in the search. Positive fp16 order == u16 order.
// ---------------------------------------------------------------------------
__global__ __launch_bounds__(256) void topk_kernel(int rgBase)
{
    __shared__ int cw[8];
    __shared__ int sTot;
    __shared__ int s_cnt;
    const int row = rgBase + blockIdx.x;
    const int t = threadIdx.x, wid = t >> 5, lane = t & 31;

    const uint4* arow = (const uint4*)((const char*)g_acts + (size_t)row * H_SZ * 2);
    uint4 q[4];
    #pragma unroll
    for (int i = 0; i < 4; i++) q[i] = arow[t + 256 * i];
    uint32_t* w = (uint32_t*)q;   // 16 u32 = 32 u16 values

    if (t == 0) s_cnt = 0;

    // binary search for T = CAND_K-th largest u16 value
    uint32_t lo = 1, hi = 0x7C00;     // count(>=1) >= K assumed; count(>=inf) = 0
    while (hi - lo > 1) {
        uint32_t mid = (lo + hi) >> 1;
        int lc = 0;
        #pragma unroll
        for (int i = 0; i < 16; i++) {
            lc += ((w[i] & 0xFFFFu) >= mid);
            lc += ((w[i] >> 16) >= mid);
        }
        #pragma unroll
        for (int off = 16; off > 0; off >>= 1)
            lc += __shfl_down_sync(0xffffffffu, lc, off);
        if (lane == 0) cw[wid] = lc;
        __syncthreads();
        if (t == 0) {
            int s = 0;
            #pragma unroll
            for (int i = 0; i < 8; i++) s += cw[i];
            sTot = s;
        }
        __syncthreads();
        if (sTot >= CAND_K) lo = mid; else hi = mid;
        __syncthreads();
    }
    const uint32_t T = lo;

    // collect candidate indices (u >= T); order irrelevant (rescore ranks totally)
    #pragma unroll
    for (int i = 0; i < 16; i++) {
        int cbase = (t + 256 * (i >> 2)) * 8 + (i & 3) * 2;
        uint32_t u0 = w[i] & 0xFFFFu, u1 = w[i] >> 16;
        if (u0 >= T) {
            int p = atomicAdd(&s_cnt, 1);
            if (p < CAND_MAX) g_cand[row * CAND_MAX + p] = cbase;
        }
        if (u1 >= T) {
            int p = atomicAdd(&s_cnt, 1);
            if (p < CAND_MAX) g_cand[row * CAND_MAX + p] = cbase + 1;
        }
    }
    __syncthreads();
    if (t == 0) g_ccnt[row] = (s_cnt < CAND_MAX) ? s_cnt : CAND_MAX;
}

// ---------------------------------------------------------------------------
// Kernel 4: exact fp32 rescore — 2 rows per block, one THREAD per candidate,
// sequential-k fmaf chain via float4 loads (identical arithmetic order).
// ---------------------------------------------------------------------------
__global__ __launch_bounds__(256) void rescore_kernel(
    const float* __restrict__ x, const float* __restrict__ W_enc,
    const float* __restrict__ b_enc, const float* __restrict__ b_dec,
    int rgBase)
{
    __shared__ float xs[2][D_SZ];
    __shared__ float cv[2][CAND_MAX];
    __shared__ int   ci[2][CAND_MAX];
    const int t = threadIdx.x;
    const int row0 = rgBase + blockIdx.x * 2;
    const int h = t >> 7, tt = t & 127;      // half 0/1 -> row0/row0+1

    xs[0][t & 255] = x[(size_t)row0 * D_SZ + t] - b_dec[t];
    xs[1][t]       = x[(size_t)(row0 + 1) * D_SZ + t] - b_dec[t];
    const int cnt = g_ccnt[row0 + h];
    __syncthreads();

    if (tt < cnt) {
        int idx = g_cand[(row0 + h) * CAND_MAX + tt];
        const float4* w4 = (const float4*)(W_enc + (size_t)idx * D_SZ);
        const float* xr = xs[h];
        float s = 0.f;
        #pragma unroll 16
        for (int k4 = 0; k4 < D_SZ / 4; k4++) {
            float4 wv = __ldg(&w4[k4]);
            s = fmaf(xr[k4 * 4 + 0], wv.x, s);
            s = fmaf(xr[k4 * 4 + 1], wv.y, s);
            s = fmaf(xr[k4 * 4 + 2], wv.z, s);
            s = fmaf(xr[k4 * 4 + 3], wv.w, s);
        }
        cv[h][tt] = fmaxf(s + b_enc[idx], 0.f);
        ci[h][tt] = idx;
    }
    __syncthreads();

    if (tt < cnt) {
        float v = cv[h][tt]; int id = ci[h][tt];
        int rank = 0;
        for (int j = 0; j < cnt; j++) {
            float vo = cv[h][j];
            rank += (vo > v) || (vo == v && ci[h][j] < id);
        }
        if (rank < K_TOP) {
            g_tkval[(row0 + h) * K_TOP + rank] = v;
            g_tkidx[(row0 + h) * K_TOP + rank] = id;
        }
    }
}

// ---------------------------------------------------------------------------
// Kernel 5: sparse decode + counts + e^2 partials
// ---------------------------------------------------------------------------
__global__ __launch_bounds__(256) void decode_kernel(
    const float* __restrict__ x, const float* __restrict__ W_dec,
    const float* __restrict__ b_dec, float* __restrict__ out, int rgBase)
{
    __shared__ float sval[8][K_TOP];
    __shared__ int   sidx[8][K_TOP];
    __shared__ float red[256];
    int r0 = rgBase + blockIdx.x * 8, t = threadIdx.x;
    {
        int r = t >> 5, j = t & 31;
        int row = r0 + r;
        sval[r][j] = g_tkval[row * K_TOP + j];
        int id = g_tkidx[row * K_TOP + j];
        sidx[r][j] = id;
        atomicAdd(&g_counts[id], 1);
    }
    __syncthreads();
    float bd = b_dec[t];
    float esum = 0.f;
    #pragma unroll
    for (int r = 0; r < 8; r++) {
        float acc = bd;
        #pragma unroll
        for (int j = 0; j < K_TOP; j++)
            acc += sval[r][j] * __ldg(&W_dec[(size_t)sidx[r][j] * D_SZ + t]);
        int row = r0 + r;
        out[(size_t)row * D_SZ + t] = acc;
        float e = acc - x[(size_t)row * D_SZ + t];
        esum += e * e;
    }
    red[t] = esum; __syncthreads();
    for (int s = 128; s > 0; s >>= 1) { if (t < s) red[t] += red[t + s]; __syncthreads(); }
    if (t == 0) g_e2part[r0 / 8] = red[0];
}

// ---------------------------------------------------------------------------
// Kernel 6: finalize
// ---------------------------------------------------------------------------
__global__ __launch_bounds__(256) void finalize_kernel(float* __restrict__ out)
{
    __shared__ float red[256];
    __shared__ float sh_var, sh_q, sh_e2;
    int t = threadIdx.x;
    float S = 0.f;
    for (int g = 0; g < 64; g++) S += g_colsum[g * D_SZ + t];
    red[t] = S * S * (1.0f / (float)B_SZ);
    __syncthreads();
    for (int s = 128; s > 0; s >>= 1) { if (t < s) red[t] += red[t + s]; __syncthreads(); }
    if (t == 0) sh_var = red[0];
    __syncthreads();
    red[t] = (t < 64) ? g_qpart[t] : 0.f;
    __syncthreads();
    for (int s = 128; s > 0; s >>= 1) { if (t < s) red[t] += red[t + s]; __syncthreads(); }
    if (t == 0) sh_q = red[0];
    __syncthreads();
    float e2 = 0.f;
    for (int i = t; i < B_SZ / 8; i += 256) e2 += g_e2part[i];
    red[t] = e2; __syncthreads();
    for (int s = 128; s > 0; s >>= 1) { if (t < s) red[t] += red[t + s]; __syncthreads(); }
    if (t == 0) sh_e2 = red[0];
    __syncthreads();
    if (t == 0) {
        float total_var = sh_q - sh_var;
        out[(size_t)B_SZ * D_SZ + H_SZ] = sh_e2 / total_var;
    }
    for (int i = t; i < H_SZ; i += 256)
        out[(size_t)B_SZ * D_SZ + i] = (float)g_counts[i];
}

// ---------------------------------------------------------------------------
// Launch: per row-group pipeline keeps the 64MB acts slab L2-resident
// ---------------------------------------------------------------------------
extern "C" void kernel_launch(void* const* d_in, const int* in_sizes, int n_in,
                              void* d_out, int out_size)
{
    const float* x     = (const float*)d_in[0];
    const float* W_enc = (const float*)d_in[1];
    const float* b_enc = (const float*)d_in[2];
    const float* W_dec = (const float*)d_in[3];
    const float* b_dec = (const float*)d_in[4];
    float* out = (float*)d_out;

    cudaFuncSetAttribute(encode_kernel,
                         cudaFuncAttributeMaxDynamicSharedMemorySize, ESM_TOTAL);

    conv_kernel<<<3072, 256>>>(x, W_enc, b_dec);
    colstat_kernel<<<64, 256>>>(x);
    for (int g = 0; g < NGRP; g++) {
        int rg = g * ROWG;
        encode_kernel<<<dim3(H_SZ / 128, ROWG / 128), 256, ESM_TOTAL>>>(b_enc, rg);
        topk_kernel<<<ROWG, 256>>>(rg);
        rescore_kernel<<<ROWG / 2, 256>>>(x, W_enc, b_enc, b_dec, rg);
        decode_kernel<<<ROWG / 8, 256>>>(x, W_dec, b_dec, out, rg);
    }
    finalize_kernel<<<1, 256>>>(out);
}

// round 7
// speedup vs baseline: 2.6387x; 1.0659x over previous
#include <cuda_runtime.h>
#include <cuda_fp16.h>
#include <cstdint>

#define B_SZ   16384
#define D_SZ   256
#define H_SZ   8192
#define K_TOP  32
#define CAND_K   48     // min acceptable candidate count at threshold
#define CAND_HI  110    // max acceptable count at threshold (early-exit window)
#define CAND_MAX 128    // candidate buffer cap
#define ROWG   4096     // row-group size (acts slab 64MB -> L2 resident)
#define NGRP   (B_SZ / ROWG)

// ---------------------------------------------------------------------------
// Scratch (__device__ globals)
// ---------------------------------------------------------------------------
__device__ __half g_xh [B_SZ * D_SZ];                 // fp16(x - b_dec)
__device__ __half g_weh[H_SZ * D_SZ];                 // fp16(W_enc)
__device__ __half g_acts[(size_t)B_SZ * H_SZ];        // fp16 relu(pre_acts)
__device__ int   g_cand[B_SZ * CAND_MAX];
__device__ int   g_ccnt[B_SZ];
__device__ float g_tkval[B_SZ * K_TOP];
__device__ int   g_tkidx[B_SZ * K_TOP];
__device__ int   g_counts[H_SZ];
__device__ float g_colsum[64 * D_SZ];
__device__ float g_qpart[64];
__device__ float g_e2part[B_SZ / 8];

// ---------------------------------------------------------------------------
// Helpers
// ---------------------------------------------------------------------------
__device__ __forceinline__ uint32_t smem_u32(const void* p) {
    uint32_t a;
    asm("{ .reg .u64 t; cvta.to.shared.u64 t, %1; cvt.u32.u64 %0, t; }" : "=r"(a) : "l"(p));
    return a;
}
#define CP_ASYNC16(dst, src) \
    asm volatile("cp.async.cg.shared.global [%0], [%1], 16;" :: "r"(dst), "l"(src))
#define CP_COMMIT() asm volatile("cp.async.commit_group;")
#define CP_WAIT(n)  asm volatile("cp.async.wait_group %0;" :: "n"(n))

__device__ __forceinline__ void ldsm_x4(uint32_t& r0, uint32_t& r1, uint32_t& r2, uint32_t& r3,
                                        uint32_t addr) {
    asm volatile("ldmatrix.sync.aligned.m8n8.x4.shared.b16 {%0,%1,%2,%3}, [%4];"
                 : "=r"(r0), "=r"(r1), "=r"(r2), "=r"(r3) : "r"(addr));
}
__device__ __forceinline__ void mma_16816(float* c, uint32_t a0, uint32_t a1, uint32_t a2,
                                          uint32_t a3, uint32_t b0, uint32_t b1) {
    asm volatile(
        "mma.sync.aligned.m16n8k16.row.col.f32.f16.f16.f32 "
        "{%0,%1,%2,%3}, {%4,%5,%6,%7}, {%8,%9}, {%0,%1,%2,%3};"
        : "+f"(c[0]), "+f"(c[1]), "+f"(c[2]), "+f"(c[3])
        : "r"(a0), "r"(a1), "r"(a2), "r"(a3), "r"(b0), "r"(b1));
}

// ---------------------------------------------------------------------------
// Kernel 0: convert x -> fp16(x - b_dec), W_enc -> fp16
// ---------------------------------------------------------------------------
__global__ __launch_bounds__(256) void conv_kernel(
    const float* __restrict__ x, const float* __restrict__ W_enc,
    const float* __restrict__ b_dec)
{
    int b = blockIdx.x, t = threadIdx.x;
    if (b < 2048) {
        size_t e0 = ((size_t)b * 256 + t) * 8;
        int col = (int)(e0 & (D_SZ - 1));
        float4 v0 = *(const float4*)(x + e0);
        float4 v1 = *(const float4*)(x + e0 + 4);
        float4 d0 = *(const float4*)(b_dec + col);
        float4 d1 = *(const float4*)(b_dec + col + 4);
        __half o[8];
        o[0]=__float2half_rn(v0.x-d0.x); o[1]=__float2half_rn(v0.y-d0.y);
        o[2]=__float2half_rn(v0.z-d0.z); o[3]=__float2half_rn(v0.w-d0.w);
        o[4]=__float2half_rn(v1.x-d1.x); o[5]=__float2half_rn(v1.y-d1.y);
        o[6]=__float2half_rn(v1.z-d1.z); o[7]=__float2half_rn(v1.w-d1.w);
        *(uint4*)(g_xh + e0) = *(uint4*)o;
    } else {
        size_t e0 = ((size_t)(b - 2048) * 256 + t) * 8;
        float4 v0 = *(const float4*)(W_enc + e0);
        float4 v1 = *(const float4*)(W_enc + e0 + 4);
        __half o[8];
        o[0]=__float2half_rn(v0.x); o[1]=__float2half_rn(v0.y);
        o[2]=__float2half_rn(v0.z); o[3]=__float2half_rn(v0.w);
        o[4]=__float2half_rn(v1.x); o[5]=__float2half_rn(v1.y);
        o[6]=__float2half_rn(v1.z); o[7]=__float2half_rn(v1.w);
        *(uint4*)(g_weh + e0) = *(uint4*)o;
    }
}

// ---------------------------------------------------------------------------
// Kernel 1: column stats of x + zero counts
// ---------------------------------------------------------------------------
__global__ __launch_bounds__(256) void colstat_kernel(const float* __restrict__ x)
{
    __shared__ float red[256];
    int g = blockIdx.x, t = threadIdx.x;
    int gid = g * 256 + t;
    if (gid < H_SZ) g_counts[gid] = 0;
    const float* xb = x + (size_t)(g * 256) * D_SZ;
    float s = 0.f, q = 0.f;
    #pragma unroll 8
    for (int r = 0; r < 256; r++) {
        float v = xb[r * D_SZ + t];
        s += v; q += v * v;
    }
    g_colsum[g * D_SZ + t] = s;
    red[t] = q; __syncthreads();
    for (int sft = 128; sft > 0; sft >>= 1) { if (t < sft) red[t] += red[t + sft]; __syncthreads(); }
    if (t == 0) g_qpart[g] = red[0];
}

// ---------------------------------------------------------------------------
// Kernel 2: encoder GEMM via mma.sync (fp16 HMMA), 128x128x256 per block
// ---------------------------------------------------------------------------
#define KC       128
#define PITCH    136
#define STG_A    (128 * PITCH * 2)
#define OFF_A0   0
#define OFF_A1   STG_A
#define OFF_B0   (2 * STG_A)
#define OFF_B1   (3 * STG_A)
#define OFF_BES  (4 * STG_A)
#define ESM_TOTAL (OFF_BES + 512)
#define STAGE_PITCH_U32 68

__global__ __launch_bounds__(256, 1) void encode_kernel(const float* __restrict__ b_enc,
                                                        int rgBase)
{
    extern __shared__ char smem[];
    const uint32_t sbase = smem_u32(smem);
    const int t = threadIdx.x;
    const int wid = t >> 5, lane = t & 31;
    const int h0 = blockIdx.x * 128;
    const int r0 = rgBase + blockIdx.y * 128;

    const int wm = wid >> 2, wn = wid & 3;
    const int m0w = wm * 64, n0w = wn * 32;

    const char* gA = (const char*)(g_xh  + (size_t)r0 * D_SZ);
    const char* gB = (const char*)(g_weh + (size_t)h0 * D_SZ);
    #pragma unroll
    for (int s = 0; s < 2; s++) {
        #pragma unroll
        for (int i = 0; i < 8; i++) {
            int idx = t + 256 * i;
            int row = idx >> 4, q = idx & 15;
            uint32_t dOff = (uint32_t)((row * PITCH + q * 8) * 2);
            size_t gOff = ((size_t)row * D_SZ + s * KC + q * 8) * 2;
            CP_ASYNC16(sbase + (s ? OFF_A1 : OFF_A0) + dOff, gA + gOff);
            CP_ASYNC16(sbase + (s ? OFF_B1 : OFF_B0) + dOff, gB + gOff);
        }
        CP_COMMIT();
    }
    ((float*)(smem + OFF_BES))[t & 127] = b_enc[h0 + (t & 127)];

    float acc[16][4];
    #pragma unroll
    for (int f = 0; f < 16; f++)
        #pragma unroll
        for (int e = 0; e < 4; e++) acc[f][e] = 0.f;

    const int aRow = lane & 15;
    const int aCol = (lane >> 4) << 3;
    const int bRow = ((lane >> 4) << 3) + (lane & 7);
    const int bCol = ((lane >> 3) & 1) << 3;

    CP_WAIT(1);
    __syncthreads();

    #pragma unroll
    for (int s = 0; s < 2; s++) {
        const uint32_t aBase = sbase + (s ? OFF_A1 : OFF_A0)
                             + ((m0w + aRow) * PITCH + aCol) * 2;
        const uint32_t bBase = sbase + (s ? OFF_B1 : OFF_B0)
                             + ((n0w + bRow) * PITCH + bCol) * 2;
        #pragma unroll
        for (int k0 = 0; k0 < KC; k0 += 16) {
            uint32_t a[4][4], b[2][4];
            #pragma unroll
            for (int i = 0; i < 4; i++)
                ldsm_x4(a[i][0], a[i][1], a[i][2], a[i][3],
                        aBase + (i * 16 * PITCH + k0) * 2);
            #pragma unroll
            for (int jp = 0; jp < 2; jp++)
                ldsm_x4(b[jp][0], b[jp][1], b[jp][2], b[jp][3],
                        bBase + (jp * 16 * PITCH + k0) * 2);
            #pragma unroll
            for (int i = 0; i < 4; i++)
                #pragma unroll
                for (int j = 0; j < 4; j++)
                    mma_16816(acc[i * 4 + j], a[i][0], a[i][1], a[i][2], a[i][3],
                              b[j >> 1][(j & 1) * 2], b[j >> 1][(j & 1) * 2 + 1]);
        }
        if (s == 0) {
            CP_WAIT(0);
            __syncthreads();
        }
    }
    __syncthreads();

    uint32_t* stg = (uint32_t*)smem;
    const float* bes = (const float*)(smem + OFF_BES);
    const int qr = lane >> 2, qc = lane & 3;
    #pragma unroll
    for (int i = 0; i < 4; i++) {
        #pragma unroll
        for (int j = 0; j < 4; j++) {
            int col = n0w + j * 8 + qc * 2;
            float b0 = bes[col], b1 = bes[col + 1];
            const float* c = acc[i * 4 + j];
            int mA = m0w + i * 16 + qr;
            float v0 = fmaxf(c[0] + b0, 0.f), v1 = fmaxf(c[1] + b1, 0.f);
            float v2 = fmaxf(c[2] + b0, 0.f), v3 = fmaxf(c[3] + b1, 0.f);
            uint32_t p0 = (uint32_t)__half_as_ushort(__float2half_rn(v0))
                        | ((uint32_t)__half_as_ushort(__float2half_rn(v1)) << 16);
            uint32_t p1 = (uint32_t)__half_as_ushort(__float2half_rn(v2))
                        | ((uint32_t)__half_as_ushort(__float2half_rn(v3)) << 16);
            stg[mA * STAGE_PITCH_U32 + (col >> 1)] = p0;
            stg[(mA + 8) * STAGE_PITCH_U32 + (col >> 1)] = p1;
        }
    }
    __syncthreads();
    #pragma unroll
    for (int i = 0; i < 8; i++) {
        int idx = t + 256 * i;
        int row = idx >> 4, q = idx & 15;
        uint4 v = *(const uint4*)((const char*)stg + row * (STAGE_PITCH_U32 * 4) + q * 16);
        *(uint4*)((char*)g_acts + ((size_t)(r0 + row) * H_SZ + h0) * 2 + q * 16) = v;
    }
}

// ---------------------------------------------------------------------------
// Kernel 3: per-row candidate selection — windowed threshold search (R6)
// with hardened fallback: any failure to land in [CAND_K, CAND_HI] within the
// statistical bracket triggers a full-range exact search for >= CAND_K.
// ---------------------------------------------------------------------------
struct TKShared { int cw[8]; int sTot; int s_cnt; };

__device__ __forceinline__ int cnt_ge(const uint32_t* w, uint32_t mid,
                                      TKShared* sh, int t, int wid, int lane)
{
    uint32_t mm = mid | (mid << 16);
    uint32_t c2 = 0;
    #pragma unroll
    for (int i = 0; i < 16; i++)
        c2 = __vadd2(c2, __vcmpgeu2(w[i], mm) & 0x00010001u);
    unsigned local = (c2 & 0xFFFFu) + (c2 >> 16);
    unsigned r = __reduce_add_sync(0xffffffffu, local);
    if (lane == 0) sh->cw[wid] = (int)r;
    __syncthreads();
    if (t == 0) {
        int s = 0;
        #pragma unroll
        for (int i = 0; i < 8; i++) s += sh->cw[i];
        sh->sTot = s;
    }
    __syncthreads();
    return sh->sTot;
}

__global__ __launch_bounds__(256) void topk_kernel(int rgBase)
{
    __shared__ TKShared sh;
    const int row = rgBase + blockIdx.x;
    const int t = threadIdx.x, wid = t >> 5, lane = t & 31;

    const uint4* arow = (const uint4*)((const char*)g_acts + (size_t)row * H_SZ * 2);
    uint4 q[4];
    #pragma unroll
    for (int i = 0; i < 4; i++) q[i] = arow[t + 256 * i];
    uint32_t* w = (uint32_t*)q;   // 32 u16 values

    if (t == 0) sh.s_cnt = 0;

    // windowed binary search over the statistically-certain bracket [1.0, 8.0]
    uint32_t lo = 0x3BFF, hi = 0x4800;
    int T = -1;
    for (int it = 0; it < 12 && hi - lo > 1; it++) {
        uint32_t mid = (lo + hi) >> 1;
        int c = cnt_ge(w, mid, &sh, t, wid, lane);
        if (c >= CAND_K) {
            lo = mid;
            if (c <= CAND_HI) { T = (int)mid; break; }
        } else hi = mid;
    }
    if (T < 0) T = (int)lo;

    // verify; full-range fallback if the bracket assumption broke
    int cF = cnt_ge(w, (uint32_t)T, &sh, t, wid, lane);
    if (cF < CAND_K) {
        lo = 1; hi = 0x7C00;
        while (hi - lo > 1) {
            uint32_t mid = (lo + hi) >> 1;
            int c = cnt_ge(w, mid, &sh, t, wid, lane);
            if (c >= CAND_K) lo = mid; else hi = mid;
        }
        T = (int)lo;
    }
    const uint32_t Tc = (T > 12) ? (uint32_t)(T - 12) : 1u;   // -12 ulp safety margin

    #pragma unroll
    for (int i = 0; i < 16; i++) {
        int cbase = (t + 256 * (i >> 2)) * 8 + (i & 3) * 2;
        uint32_t u0 = w[i] & 0xFFFFu, u1 = w[i] >> 16;
        if (u0 >= Tc) {
            int p = atomicAdd(&sh.s_cnt, 1);
            if (p < CAND_MAX) g_cand[row * CAND_MAX + p] = cbase;
        }
        if (u1 >= Tc) {
            int p = atomicAdd(&sh.s_cnt, 1);
            if (p < CAND_MAX) g_cand[row * CAND_MAX + p] = cbase + 1;
        }
    }
    __syncthreads();
    if (t == 0) g_ccnt[row] = (sh.s_cnt < CAND_MAX) ? sh.s_cnt : CAND_MAX;
}

// ---------------------------------------------------------------------------
// Kernel 4: exact fp32 rescore — R5 VERBATIM (passing config): 2 rows/block,
// one THREAD per candidate, sequential-k fmaf chain via float4 loads.
// Summation order must stay sequential (near-tie ranking matches reference).
// ---------------------------------------------------------------------------
__global__ __launch_bounds__(256) void rescore_kernel(
    const float* __restrict__ x, const float* __restrict__ W_enc,
    const float* __restrict__ b_enc, const float* __restrict__ b_dec,
    int rgBase)
{
    __shared__ float xs[2][D_SZ];
    __shared__ float cv[2][CAND_MAX];
    __shared__ int   ci[2][CAND_MAX];
    const int t = threadIdx.x;
    const int row0 = rgBase + blockIdx.x * 2;
    const int h = t >> 7, tt = t & 127;      // half 0/1 -> row0/row0+1

    xs[0][t & 255] = x[(size_t)row0 * D_SZ + t] - b_dec[t];
    xs[1][t]       = x[(size_t)(row0 + 1) * D_SZ + t] - b_dec[t];
    const int cnt = g_ccnt[row0 + h];
    __syncthreads();

    if (tt < cnt) {
        int idx = g_cand[(row0 + h) * CAND_MAX + tt];
        const float4* w4 = (const float4*)(W_enc + (size_t)idx * D_SZ);
        const float* xr = xs[h];
        float s = 0.f;
        #pragma unroll 16
        for (int k4 = 0; k4 < D_SZ / 4; k4++) {
            float4 wv = __ldg(&w4[k4]);
            s = fmaf(xr[k4 * 4 + 0], wv.x, s);
            s = fmaf(xr[k4 * 4 + 1], wv.y, s);
            s = fmaf(xr[k4 * 4 + 2], wv.z, s);
            s = fmaf(xr[k4 * 4 + 3], wv.w, s);
        }
        cv[h][tt] = fmaxf(s + b_enc[idx], 0.f);
        ci[h][tt] = idx;
    }
    __syncthreads();

    if (tt < cnt) {
        float v = cv[h][tt]; int id = ci[h][tt];
        int rank = 0;
        for (int j = 0; j < cnt; j++) {
            float vo = cv[h][j];
            rank += (vo > v) || (vo == v && ci[h][j] < id);
        }
        if (rank < K_TOP) {
            g_tkval[(row0 + h) * K_TOP + rank] = v;
            g_tkidx[(row0 + h) * K_TOP + rank] = id;
        }
    }
}

// ---------------------------------------------------------------------------
// Kernel 5: sparse decode + counts + e^2 partials
// ---------------------------------------------------------------------------
__global__ __launch_bounds__(256) void decode_kernel(
    const float* __restrict__ x, const float* __restrict__ W_dec,
    const float* __restrict__ b_dec, float* __restrict__ out, int rgBase)
{
    __shared__ float sval[8][K_TOP];
    __shared__ int   sidx[8][K_TOP];
    __shared__ float red[256];
    int r0 = rgBase + blockIdx.x * 8, t = threadIdx.x;
    {
        int r = t >> 5, j = t & 31;
        int row = r0 + r;
        sval[r][j] = g_tkval[row * K_TOP + j];
        int id = g_tkidx[row * K_TOP + j];
        sidx[r][j] = id;
        atomicAdd(&g_counts[id], 1);
    }
    __syncthreads();
    float bd = b_dec[t];
    float esum = 0.f;
    #pragma unroll
    for (int r = 0; r < 8; r++) {
        float acc = bd;
        #pragma unroll
        for (int j = 0; j < K_TOP; j++)
            acc += sval[r][j] * __ldg(&W_dec[(size_t)sidx[r][j] * D_SZ + t]);
        int row = r0 + r;
        out[(size_t)row * D_SZ + t] = acc;
        float e = acc - x[(size_t)row * D_SZ + t];
        esum += e * e;
    }
    red[t] = esum; __syncthreads();
    for (int s = 128; s > 0; s >>= 1) { if (t < s) red[t] += red[t + s]; __syncthreads(); }
    if (t == 0) g_e2part[r0 / 8] = red[0];
}

// ---------------------------------------------------------------------------
// Kernel 6: finalize
// ---------------------------------------------------------------------------
__global__ __launch_bounds__(256) void finalize_kernel(float* __restrict__ out)
{
    __shared__ float red[256];
    __shared__ float sh_var, sh_q, sh_e2;
    int t = threadIdx.x;
    float S = 0.f;
    for (int g = 0; g < 64; g++) S += g_colsum[g * D_SZ + t];
    red[t] = S * S * (1.0f / (float)B_SZ);
    __syncthreads();
    for (int s = 128; s > 0; s >>= 1) { if (t < s) red[t] += red[t + s]; __syncthreads(); }
    if (t == 0) sh_var = red[0];
    __syncthreads();
    red[t] = (t < 64) ? g_qpart[t] : 0.f;
    __syncthreads();
    for (int s = 128; s > 0; s >>= 1) { if (t < s) red[t] += red[t + s]; __syncthreads(); }
    if (t == 0) sh_q = red[0];
    __syncthreads();
    float e2 = 0.f;
    for (int i = t; i < B_SZ / 8; i += 256) e2 += g_e2part[i];
    red[t] = e2; __syncthreads();
    for (int s = 128; s > 0; s >>= 1) { if (t < s) red[t] += red[t + s]; __syncthreads(); }
    if (t == 0) sh_e2 = red[0];
    __syncthreads();
    if (t == 0) {
        float total_var = sh_q - sh_var;
        out[(size_t)B_SZ * D_SZ + H_SZ] = sh_e2 / total_var;
    }
    for (int i = t; i < H_SZ; i += 256)
        out[(size_t)B_SZ * D_SZ + i] = (float)g_counts[i];
}

// ---------------------------------------------------------------------------
// Launch
// ---------------------------------------------------------------------------
extern "C" void kernel_launch(void* const* d_in, const int* in_sizes, int n_in,
                              void* d_out, int out_size)
{
    const float* x     = (const float*)d_in[0];
    const float* W_enc = (const float*)d_in[1];
    const float* b_enc = (const float*)d_in[2];
    const float* W_dec = (const float*)d_in[3];
    const float* b_dec = (const float*)d_in[4];
    float* out = (float*)d_out;

    cudaFuncSetAttribute(encode_kernel,
                         cudaFuncAttributeMaxDynamicSharedMemorySize, ESM_TOTAL);

    conv_kernel<<<3072, 256>>>(x, W_enc, b_dec);
    colstat_kernel<<<64, 256>>>(x);
    for (int g = 0; g < NGRP; g++) {
        int rg = g * ROWG;
        encode_kernel<<<dim3(H_SZ / 128, ROWG / 128), 256, ESM_TOTAL>>>(b_enc, rg);
        topk_kernel<<<ROWG, 256>>>(rg);
        rescore_kernel<<<ROWG / 2, 256>>>(x, W_enc, b_enc, b_dec, rg);
        decode_kernel<<<ROWG / 8, 256>>>(x, W_dec, b_dec, out, rg);
    }
    finalize_kernel<<<1, 256>>>(out);
}

// round 8
// speedup vs baseline: 2.9912x; 1.1336x over previous
#include <cuda_runtime.h>
#include <cuda_fp16.h>
#include <cstdint>

#define B_SZ   16384
#define D_SZ   256
#define H_SZ   8192
#define K_TOP  32
#define CAND_K   40     // min acceptable candidate count at threshold
#define CAND_HI  64     // max acceptable count at threshold (early-exit window)
#define CAND_MAX 96     // candidate buffer cap
#define TK_MARGIN 4     // ulp margin below threshold (2*delta proof + 2x headroom)
#define ROWG   4096     // row-group size (acts slab 64MB -> L2 resident)
#define NGRP   (B_SZ / ROWG)

// rescore staging
#define RS_BATCH 48
#define RS_PITCH 260    // words per staged row (1040B: 16B-aligned, bank-skewed)
#define RS_SMEM_FLOATS (256 + CAND_MAX + CAND_MAX + RS_BATCH * RS_PITCH)
#define RS_SMEM_BYTES  (RS_SMEM_FLOATS * 4)

// ---------------------------------------------------------------------------
// Scratch (__device__ globals)
// ---------------------------------------------------------------------------
__device__ __half g_xh [B_SZ * D_SZ];                 // fp16(x - b_dec)
__device__ __half g_weh[H_SZ * D_SZ];                 // fp16(W_enc)
__device__ __half g_acts[(size_t)B_SZ * H_SZ];        // fp16 relu(pre_acts)
__device__ int   g_cand[B_SZ * CAND_MAX];
__device__ int   g_ccnt[B_SZ];
__device__ float g_tkval[B_SZ * K_TOP];
__device__ int   g_tkidx[B_SZ * K_TOP];
__device__ int   g_counts[H_SZ];
__device__ float g_colsum[64 * D_SZ];
__device__ float g_qpart[64];
__device__ float g_e2part[B_SZ / 8];

// ---------------------------------------------------------------------------
// Helpers
// ---------------------------------------------------------------------------
__device__ __forceinline__ uint32_t smem_u32(const void* p) {
    uint32_t a;
    asm("{ .reg .u64 t; cvta.to.shared.u64 t, %1; cvt.u32.u64 %0, t; }" : "=r"(a) : "l"(p));
    return a;
}
#define CP_ASYNC16(dst, src) \
    asm volatile("cp.async.cg.shared.global [%0], [%1], 16;" :: "r"(dst), "l"(src))
#define CP_COMMIT() asm volatile("cp.async.commit_group;")
#define CP_WAIT(n)  asm volatile("cp.async.wait_group %0;" :: "n"(n))

__device__ __forceinline__ void ldsm_x4(uint32_t& r0, uint32_t& r1, uint32_t& r2, uint32_t& r3,
                                        uint32_t addr) {
    asm volatile("ldmatrix.sync.aligned.m8n8.x4.shared.b16 {%0,%1,%2,%3}, [%4];"
                 : "=r"(r0), "=r"(r1), "=r"(r2), "=r"(r3) : "r"(addr));
}
__device__ __forceinline__ void mma_16816(float* c, uint32_t a0, uint32_t a1, uint32_t a2,
                                          uint32_t a3, uint32_t b0, uint32_t b1) {
    asm volatile(
        "mma.sync.aligned.m16n8k16.row.col.f32.f16.f16.f32 "
        "{%0,%1,%2,%3}, {%4,%5,%6,%7}, {%8,%9}, {%0,%1,%2,%3};"
        : "+f"(c[0]), "+f"(c[1]), "+f"(c[2]), "+f"(c[3])
        : "r"(a0), "r"(a1), "r"(a2), "r"(a3), "r"(b0), "r"(b1));
}

// ---------------------------------------------------------------------------
// Kernel 0: convert x -> fp16(x - b_dec), W_enc -> fp16
// ---------------------------------------------------------------------------
__global__ __launch_bounds__(256) void conv_kernel(
    const float* __restrict__ x, const float* __restrict__ W_enc,
    const float* __restrict__ b_dec)
{
    int b = blockIdx.x, t = threadIdx.x;
    if (b < 2048) {
        size_t e0 = ((size_t)b * 256 + t) * 8;
        int col = (int)(e0 & (D_SZ - 1));
        float4 v0 = *(const float4*)(x + e0);
        float4 v1 = *(const float4*)(x + e0 + 4);
        float4 d0 = *(const float4*)(b_dec + col);
        float4 d1 = *(const float4*)(b_dec + col + 4);
        __half o[8];
        o[0]=__float2half_rn(v0.x-d0.x); o[1]=__float2half_rn(v0.y-d0.y);
        o[2]=__float2half_rn(v0.z-d0.z); o[3]=__float2half_rn(v0.w-d0.w);
        o[4]=__float2half_rn(v1.x-d1.x); o[5]=__float2half_rn(v1.y-d1.y);
        o[6]=__float2half_rn(v1.z-d1.z); o[7]=__float2half_rn(v1.w-d1.w);
        *(uint4*)(g_xh + e0) = *(uint4*)o;
    } else {
        size_t e0 = ((size_t)(b - 2048) * 256 + t) * 8;
        float4 v0 = *(const float4*)(W_enc + e0);
        float4 v1 = *(const float4*)(W_enc + e0 + 4);
        __half o[8];
        o[0]=__float2half_rn(v0.x); o[1]=__float2half_rn(v0.y);
        o[2]=__float2half_rn(v0.z); o[3]=__float2half_rn(v0.w);
        o[4]=__float2half_rn(v1.x); o[5]=__float2half_rn(v1.y);
        o[6]=__float2half_rn(v1.z); o[7]=__float2half_rn(v1.w);
        *(uint4*)(g_weh + e0) = *(uint4*)o;
    }
}

// ---------------------------------------------------------------------------
// Kernel 1: column stats of x + zero counts
// ---------------------------------------------------------------------------
__global__ __launch_bounds__(256) void colstat_kernel(const float* __restrict__ x)
{
    __shared__ float red[256];
    int g = blockIdx.x, t = threadIdx.x;
    int gid = g * 256 + t;
    if (gid < H_SZ) g_counts[gid] = 0;
    const float* xb = x + (size_t)(g * 256) * D_SZ;
    float s = 0.f, q = 0.f;
    #pragma unroll 8
    for (int r = 0; r < 256; r++) {
        float v = xb[r * D_SZ + t];
        s += v; q += v * v;
    }
    g_colsum[g * D_SZ + t] = s;
    red[t] = q; __syncthreads();
    for (int sft = 128; sft > 0; sft >>= 1) { if (t < sft) red[t] += red[t + sft]; __syncthreads(); }
    if (t == 0) g_qpart[g] = red[0];
}

// ---------------------------------------------------------------------------
// Kernel 2: encoder GEMM via mma.sync (fp16 HMMA), 128x128x256 per block
// ---------------------------------------------------------------------------
#define KC       128
#define PITCH    136
#define STG_A    (128 * PITCH * 2)
#define OFF_A0   0
#define OFF_A1   STG_A
#define OFF_B0   (2 * STG_A)
#define OFF_B1   (3 * STG_A)
#define OFF_BES  (4 * STG_A)
#define ESM_TOTAL (OFF_BES + 512)
#define STAGE_PITCH_U32 68

__global__ __launch_bounds__(256, 1) void encode_kernel(const float* __restrict__ b_enc,
                                                        int rgBase)
{
    extern __shared__ char smem[];
    const uint32_t sbase = smem_u32(smem);
    const int t = threadIdx.x;
    const int wid = t >> 5, lane = t & 31;
    const int h0 = blockIdx.x * 128;
    const int r0 = rgBase + blockIdx.y * 128;

    const int wm = wid >> 2, wn = wid & 3;
    const int m0w = wm * 64, n0w = wn * 32;

    const char* gA = (const char*)(g_xh  + (size_t)r0 * D_SZ);
    const char* gB = (const char*)(g_weh + (size_t)h0 * D_SZ);
    #pragma unroll
    for (int s = 0; s < 2; s++) {
        #pragma unroll
        for (int i = 0; i < 8; i++) {
            int idx = t + 256 * i;
            int row = idx >> 4, q = idx & 15;
            uint32_t dOff = (uint32_t)((row * PITCH + q * 8) * 2);
            size_t gOff = ((size_t)row * D_SZ + s * KC + q * 8) * 2;
            CP_ASYNC16(sbase + (s ? OFF_A1 : OFF_A0) + dOff, gA + gOff);
            CP_ASYNC16(sbase + (s ? OFF_B1 : OFF_B0) + dOff, gB + gOff);
        }
        CP_COMMIT();
    }
    ((float*)(smem + OFF_BES))[t & 127] = b_enc[h0 + (t & 127)];

    float acc[16][4];
    #pragma unroll
    for (int f = 0; f < 16; f++)
        #pragma unroll
        for (int e = 0; e < 4; e++) acc[f][e] = 0.f;

    const int aRow = lane & 15;
    const int aCol = (lane >> 4) << 3;
    const int bRow = ((lane >> 4) << 3) + (lane & 7);
    const int bCol = ((lane >> 3) & 1) << 3;

    CP_WAIT(1);
    __syncthreads();

    #pragma unroll
    for (int s = 0; s < 2; s++) {
        const uint32_t aBase = sbase + (s ? OFF_A1 : OFF_A0)
                             + ((m0w + aRow) * PITCH + aCol) * 2;
        const uint32_t bBase = sbase + (s ? OFF_B1 : OFF_B0)
                             + ((n0w + bRow) * PITCH + bCol) * 2;
        #pragma unroll
        for (int k0 = 0; k0 < KC; k0 += 16) {
            uint32_t a[4][4], b[2][4];
            #pragma unroll
            for (int i = 0; i < 4; i++)
                ldsm_x4(a[i][0], a[i][1], a[i][2], a[i][3],
                        aBase + (i * 16 * PITCH + k0) * 2);
            #pragma unroll
            for (int jp = 0; jp < 2; jp++)
                ldsm_x4(b[jp][0], b[jp][1], b[jp][2], b[jp][3],
                        bBase + (jp * 16 * PITCH + k0) * 2);
            #pragma unroll
            for (int i = 0; i < 4; i++)
                #pragma unroll
                for (int j = 0; j < 4; j++)
                    mma_16816(acc[i * 4 + j], a[i][0], a[i][1], a[i][2], a[i][3],
                              b[j >> 1][(j & 1) * 2], b[j >> 1][(j & 1) * 2 + 1]);
        }
        if (s == 0) {
            CP_WAIT(0);
            __syncthreads();
        }
    }
    __syncthreads();

    uint32_t* stg = (uint32_t*)smem;
    const float* bes = (const float*)(smem + OFF_BES);
    const int qr = lane >> 2, qc = lane & 3;
    #pragma unroll
    for (int i = 0; i < 4; i++) {
        #pragma unroll
        for (int j = 0; j < 4; j++) {
            int col = n0w + j * 8 + qc * 2;
            float b0 = bes[col], b1 = bes[col + 1];
            const float* c = acc[i * 4 + j];
            int mA = m0w + i * 16 + qr;
            float v0 = fmaxf(c[0] + b0, 0.f), v1 = fmaxf(c[1] + b1, 0.f);
            float v2 = fmaxf(c[2] + b0, 0.f), v3 = fmaxf(c[3] + b1, 0.f);
            uint32_t p0 = (uint32_t)__half_as_ushort(__float2half_rn(v0))
                        | ((uint32_t)__half_as_ushort(__float2half_rn(v1)) << 16);
            uint32_t p1 = (uint32_t)__half_as_ushort(__float2half_rn(v2))
                        | ((uint32_t)__half_as_ushort(__float2half_rn(v3)) << 16);
            stg[mA * STAGE_PITCH_U32 + (col >> 1)] = p0;
            stg[(mA + 8) * STAGE_PITCH_U32 + (col >> 1)] = p1;
        }
    }
    __syncthreads();
    #pragma unroll
    for (int i = 0; i < 8; i++) {
        int idx = t + 256 * i;
        int row = idx >> 4, q = idx & 15;
        uint4 v = *(const uint4*)((const char*)stg + row * (STAGE_PITCH_U32 * 4) + q * 16);
        *(uint4*)((char*)g_acts + ((size_t)(r0 + row) * H_SZ + h0) * 2 + q * 16) = v;
    }
}

// ---------------------------------------------------------------------------
// Kernel 3: per-row candidate selection — windowed threshold search,
// tightened window [40,64] and -4ulp margin (proof: need only 2*delta ~ 2ulp).
// ---------------------------------------------------------------------------
struct TKShared { int cw[8]; int sTot; int s_cnt; };

__device__ __forceinline__ int cnt_ge(const uint32_t* w, uint32_t mid,
                                      TKShared* sh, int t, int wid, int lane)
{
    uint32_t mm = mid | (mid << 16);
    uint32_t c2 = 0;
    #pragma unroll
    for (int i = 0; i < 16; i++)
        c2 = __vadd2(c2, __vcmpgeu2(w[i], mm) & 0x00010001u);
    unsigned local = (c2 & 0xFFFFu) + (c2 >> 16);
    unsigned r = __reduce_add_sync(0xffffffffu, local);
    if (lane == 0) sh->cw[wid] = (int)r;
    __syncthreads();
    if (t == 0) {
        int s = 0;
        #pragma unroll
        for (int i = 0; i < 8; i++) s += sh->cw[i];
        sh->sTot = s;
    }
    __syncthreads();
    return sh->sTot;
}

__global__ __launch_bounds__(256) void topk_kernel(int rgBase)
{
    __shared__ TKShared sh;
    const int row = rgBase + blockIdx.x;
    const int t = threadIdx.x, wid = t >> 5, lane = t & 31;

    const uint4* arow = (const uint4*)((const char*)g_acts + (size_t)row * H_SZ * 2);
    uint4 q[4];
    #pragma unroll
    for (int i = 0; i < 4; i++) q[i] = arow[t + 256 * i];
    uint32_t* w = (uint32_t*)q;   // 32 u16 values

    if (t == 0) sh.s_cnt = 0;

    // windowed binary search over the statistically-certain bracket [1.0, 8.0]
    uint32_t lo = 0x3BFF, hi = 0x4800;
    int T = -1;
    for (int it = 0; it < 12 && hi - lo > 1; it++) {
        uint32_t mid = (lo + hi) >> 1;
        int c = cnt_ge(w, mid, &sh, t, wid, lane);
        if (c >= CAND_K) {
            lo = mid;
            if (c <= CAND_HI) { T = (int)mid; break; }
        } else hi = mid;
    }
    if (T < 0) T = (int)lo;

    // verify; full-range fallback if the bracket assumption broke
    int cF = cnt_ge(w, (uint32_t)T, &sh, t, wid, lane);
    if (cF < CAND_K) {
        lo = 1; hi = 0x7C00;
        while (hi - lo > 1) {
            uint32_t mid = (lo + hi) >> 1;
            int c = cnt_ge(w, mid, &sh, t, wid, lane);
            if (c >= CAND_K) lo = mid; else hi = mid;
        }
        T = (int)lo;
    }
    const uint32_t Tc = (T > TK_MARGIN) ? (uint32_t)(T - TK_MARGIN) : 1u;

    #pragma unroll
    for (int i = 0; i < 16; i++) {
        int cbase = (t + 256 * (i >> 2)) * 8 + (i & 3) * 2;
        uint32_t u0 = w[i] & 0xFFFFu, u1 = w[i] >> 16;
        if (u0 >= Tc) {
            int p = atomicAdd(&sh.s_cnt, 1);
            if (p < CAND_MAX) g_cand[row * CAND_MAX + p] = cbase;
        }
        if (u1 >= Tc) {
            int p = atomicAdd(&sh.s_cnt, 1);
            if (p < CAND_MAX) g_cand[row * CAND_MAX + p] = cbase + 1;
        }
    }
    __syncthreads();
    if (t == 0) g_ccnt[row] = (sh.s_cnt < CAND_MAX) ? sh.s_cnt : CAND_MAX;
}

// ---------------------------------------------------------------------------
// Kernel 4: exact fp32 rescore — one block per row; candidate W_enc rows are
// STAGED into smem with coalesced float4 loads (pitch 260 words), then each
// candidate's score is the VERBATIM sequential fmaf chain (same floats, same
// order as the passing R5/R7 config — only the load path changed).
// ---------------------------------------------------------------------------
__global__ __launch_bounds__(256) void rescore_kernel(
    const float* __restrict__ x, const float* __restrict__ W_enc,
    const float* __restrict__ b_enc, const float* __restrict__ b_dec,
    int rgBase)
{
    extern __shared__ float sm[];
    float* xs  = sm;                       // [256]
    float* cv  = sm + 256;                 // [CAND_MAX]
    int*   ci  = (int*)(sm + 256 + CAND_MAX);
    float* stg = sm + 256 + 2 * CAND_MAX;  // [RS_BATCH][RS_PITCH]

    const int row = rgBase + blockIdx.x;
    const int t = threadIdx.x;

    xs[t] = x[(size_t)row * D_SZ + t] - b_dec[t];
    const int cnt = g_ccnt[row];
    __syncthreads();

    for (int b0 = 0; b0 < cnt; b0 += RS_BATCH) {
        int nb = min(RS_BATCH, cnt - b0);
        // coalesced staging: 64 consecutive threads load one row's 64 float4s
        for (int j = t; j < nb * 64; j += 256) {
            int r = j >> 6, c4 = j & 63;
            int idx = g_cand[row * CAND_MAX + b0 + r];
            float4 v = __ldg((const float4*)(W_enc + (size_t)idx * D_SZ) + c4);
            *(float4*)(stg + r * RS_PITCH + c4 * 4) = v;
        }
        __syncthreads();
        if (t < nb) {
            int idx = g_cand[row * CAND_MAX + b0 + t];
            const float* wrow = stg + t * RS_PITCH;
            float s = 0.f;
            #pragma unroll 8
            for (int k = 0; k < D_SZ; k++) s = fmaf(xs[k], wrow[k], s);
            cv[b0 + t] = fmaxf(s + b_enc[idx], 0.f);
            ci[b0 + t] = idx;
        }
        __syncthreads();
    }

    if (t < cnt) {
        float v = cv[t]; int id = ci[t];
        int rank = 0;
        for (int j = 0; j < cnt; j++) {
            float vo = cv[j];
            rank += (vo > v) || (vo == v && ci[j] < id);
        }
        if (rank < K_TOP) {
            g_tkval[row * K_TOP + rank] = v;
            g_tkidx[row * K_TOP + rank] = id;
        }
    }
}

// ---------------------------------------------------------------------------
// Kernel 5: sparse decode + counts + e^2 partials
// ---------------------------------------------------------------------------
__global__ __launch_bounds__(256) void decode_kernel(
    const float* __restrict__ x, const float* __restrict__ W_dec,
    const float* __restrict__ b_dec, float* __restrict__ out, int rgBase)
{
    __shared__ float sval[8][K_TOP];
    __shared__ int   sidx[8][K_TOP];
    __shared__ float red[256];
    int r0 = rgBase + blockIdx.x * 8, t = threadIdx.x;
    {
        int r = t >> 5, j = t & 31;
        int row = r0 + r;
        sval[r][j] = g_tkval[row * K_TOP + j];
        int id = g_tkidx[row * K_TOP + j];
        sidx[r][j] = id;
        atomicAdd(&g_counts[id], 1);
    }
    __syncthreads();
    float bd = b_dec[t];
    float esum = 0.f;
    #pragma unroll
    for (int r = 0; r < 8; r++) {
        float acc = bd;
        #pragma unroll
        for (int j = 0; j < K_TOP; j++)
            acc += sval[r][j] * __ldg(&W_dec[(size_t)sidx[r][j] * D_SZ + t]);
        int row = r0 + r;
        out[(size_t)row * D_SZ + t] = acc;
        float e = acc - x[(size_t)row * D_SZ + t];
        esum += e * e;
    }
    red[t] = esum; __syncthreads();
    for (int s = 128; s > 0; s >>= 1) { if (t < s) red[t] += red[t + s]; __syncthreads(); }
    if (t == 0) g_e2part[r0 / 8] = red[0];
}

// ---------------------------------------------------------------------------
// Kernel 6: finalize
// ---------------------------------------------------------------------------
__global__ __launch_bounds__(256) void finalize_kernel(float* __restrict__ out)
{
    __shared__ float red[256];
    __shared__ float sh_var, sh_q, sh_e2;
    int t = threadIdx.x;
    float S = 0.f;
    for (int g = 0; g < 64; g++) S += g_colsum[g * D_SZ + t];
    red[t] = S * S * (1.0f / (float)B_SZ);
    __syncthreads();
    for (int s = 128; s > 0; s >>= 1) { if (t < s) red[t] += red[t + s]; __syncthreads(); }
    if (t == 0) sh_var = red[0];
    __syncthreads();
    red[t] = (t < 64) ? g_qpart[t] : 0.f;
    __syncthreads();
    for (int s = 128; s > 0; s >>= 1) { if (t < s) red[t] += red[t + s]; __syncthreads(); }
    if (t == 0) sh_q = red[0];
    __syncthreads();
    float e2 = 0.f;
    for (int i = t; i < B_SZ / 8; i += 256) e2 += g_e2part[i];
    red[t] = e2; __syncthreads();
    for (int s = 128; s > 0; s >>= 1) { if (t < s) red[t] += red[t + s]; __syncthreads(); }
    if (t == 0) sh_e2 = red[0];
    __syncthreads();
    if (t == 0) {
        float total_var = sh_q - sh_var;
        out[(size_t)B_SZ * D_SZ + H_SZ] = sh_e2 / total_var;
    }
    for (int i = t; i < H_SZ; i += 256)
        out[(size_t)B_SZ * D_SZ + i] = (float)g_counts[i];
}

// ---------------------------------------------------------------------------
// Launch
// ---------------------------------------------------------------------------
extern "C" void kernel_launch(void* const* d_in, const int* in_sizes, int n_in,
                              void* d_out, int out_size)
{
    const float* x     = (const float*)d_in[0];
    const float* W_enc = (const float*)d_in[1];
    const float* b_enc = (const float*)d_in[2];
    const float* W_dec = (const float*)d_in[3];
    const float* b_dec = (const float*)d_in[4];
    float* out = (float*)d_out;

    cudaFuncSetAttribute(encode_kernel,
                         cudaFuncAttributeMaxDynamicSharedMemorySize, ESM_TOTAL);
    cudaFuncSetAttribute(rescore_kernel,
                         cudaFuncAttributeMaxDynamicSharedMemorySize, RS_SMEM_BYTES);

    conv_kernel<<<3072, 256>>>(x, W_enc, b_dec);
    colstat_kernel<<<64, 256>>>(x);
    for (int g = 0; g < NGRP; g++) {
        int rg = g * ROWG;
        encode_kernel<<<dim3(H_SZ / 128, ROWG / 128), 256, ESM_TOTAL>>>(b_enc, rg);
        topk_kernel<<<ROWG, 256>>>(rg);
        rescore_kernel<<<ROWG, 256, RS_SMEM_BYTES>>>(x, W_enc, b_enc, b_dec, rg);
        decode_kernel<<<ROWG / 8, 256>>>(x, W_dec, b_dec, out, rg);
    }
    finalize_kernel<<<1, 256>>>(out);
}

// round 9
// speedup vs baseline: 3.5244x; 1.1783x over previous
#include <cuda_runtime.h>
#include <cuda_fp16.h>
#include <cstdint>

#define B_SZ   16384
#define D_SZ   256
#define H_SZ   8192
#define K_TOP  32
#define CAND_K   40     // min acceptable candidate count at threshold
#define CAND_HI  64     // max acceptable count at threshold (early-exit window)
#define CAND_MAX 96     // candidate buffer cap
#define TK_MARGIN 4     // ulp margin below threshold
#define ROWG   4096     // row-group size (acts slab 64MB -> L2 resident)
#define NGRP   (B_SZ / ROWG)

// select (fused topk+rescore) staging
#define RS_BATCH 48
#define RS_PITCH 260    // words per staged row (1040B: 16B-aligned, bank-skewed)
#define SEL_SMEM_FLOATS (256 + CAND_MAX + CAND_MAX + RS_BATCH * RS_PITCH)
#define SEL_SMEM_BYTES  (SEL_SMEM_FLOATS * 4)

// ---------------------------------------------------------------------------
// Scratch (__device__ globals)
// ---------------------------------------------------------------------------
__device__ __half g_xh [B_SZ * D_SZ];                 // fp16(x - b_dec)
__device__ __half g_weh[H_SZ * D_SZ];                 // fp16(W_enc)
__device__ __half g_acts[(size_t)B_SZ * H_SZ];        // fp16 relu(pre_acts)
__device__ float g_tkval[B_SZ * K_TOP];
__device__ int   g_tkidx[B_SZ * K_TOP];
__device__ int   g_counts[H_SZ];
__device__ float g_colsum[64 * D_SZ];
__device__ float g_qpart[64];
__device__ float g_e2part[B_SZ / 8];

// ---------------------------------------------------------------------------
// Helpers
// ---------------------------------------------------------------------------
__device__ __forceinline__ uint32_t smem_u32(const void* p) {
    uint32_t a;
    asm("{ .reg .u64 t; cvta.to.shared.u64 t, %1; cvt.u32.u64 %0, t; }" : "=r"(a) : "l"(p));
    return a;
}
#define CP_ASYNC16(dst, src) \
    asm volatile("cp.async.cg.shared.global [%0], [%1], 16;" :: "r"(dst), "l"(src))
#define CP_COMMIT() asm volatile("cp.async.commit_group;")
#define CP_WAIT(n)  asm volatile("cp.async.wait_group %0;" :: "n"(n))

__device__ __forceinline__ void ldsm_x4(uint32_t& r0, uint32_t& r1, uint32_t& r2, uint32_t& r3,
                                        uint32_t addr) {
    asm volatile("ldmatrix.sync.aligned.m8n8.x4.shared.b16 {%0,%1,%2,%3}, [%4];"
                 : "=r"(r0), "=r"(r1), "=r"(r2), "=r"(r3) : "r"(addr));
}
__device__ __forceinline__ void mma_16816(float* c, uint32_t a0, uint32_t a1, uint32_t a2,
                                          uint32_t a3, uint32_t b0, uint32_t b1) {
    asm volatile(
        "mma.sync.aligned.m16n8k16.row.col.f32.f16.f16.f32 "
        "{%0,%1,%2,%3}, {%4,%5,%6,%7}, {%8,%9}, {%0,%1,%2,%3};"
        : "+f"(c[0]), "+f"(c[1]), "+f"(c[2]), "+f"(c[3])
        : "r"(a0), "r"(a1), "r"(a2), "r"(a3), "r"(b0), "r"(b1));
}

// ---------------------------------------------------------------------------
// Kernel 0: convert x -> fp16(x - b_dec), W_enc -> fp16
// ---------------------------------------------------------------------------
__global__ __launch_bounds__(256) void conv_kernel(
    const float* __restrict__ x, const float* __restrict__ W_enc,
    const float* __restrict__ b_dec)
{
    int b = blockIdx.x, t = threadIdx.x;
    if (b < 2048) {
        size_t e0 = ((size_t)b * 256 + t) * 8;
        int col = (int)(e0 & (D_SZ - 1));
        float4 v0 = *(const float4*)(x + e0);
        float4 v1 = *(const float4*)(x + e0 + 4);
        float4 d0 = *(const float4*)(b_dec + col);
        float4 d1 = *(const float4*)(b_dec + col + 4);
        __half o[8];
        o[0]=__float2half_rn(v0.x-d0.x); o[1]=__float2half_rn(v0.y-d0.y);
        o[2]=__float2half_rn(v0.z-d0.z); o[3]=__float2half_rn(v0.w-d0.w);
        o[4]=__float2half_rn(v1.x-d1.x); o[5]=__float2half_rn(v1.y-d1.y);
        o[6]=__float2half_rn(v1.z-d1.z); o[7]=__float2half_rn(v1.w-d1.w);
        *(uint4*)(g_xh + e0) = *(uint4*)o;
    } else {
        size_t e0 = ((size_t)(b - 2048) * 256 + t) * 8;
        float4 v0 = *(const float4*)(W_enc + e0);
        float4 v1 = *(const float4*)(W_enc + e0 + 4);
        __half o[8];
        o[0]=__float2half_rn(v0.x); o[1]=__float2half_rn(v0.y);
        o[2]=__float2half_rn(v0.z); o[3]=__float2half_rn(v0.w);
        o[4]=__float2half_rn(v1.x); o[5]=__float2half_rn(v1.y);
        o[6]=__float2half_rn(v1.z); o[7]=__float2half_rn(v1.w);
        *(uint4*)(g_weh + e0) = *(uint4*)o;
    }
}

// ---------------------------------------------------------------------------
// Kernel 1: column stats of x + zero counts
// ---------------------------------------------------------------------------
__global__ __launch_bounds__(256) void colstat_kernel(const float* __restrict__ x)
{
    __shared__ float red[256];
    int g = blockIdx.x, t = threadIdx.x;
    int gid = g * 256 + t;
    if (gid < H_SZ) g_counts[gid] = 0;
    const float* xb = x + (size_t)(g * 256) * D_SZ;
    float s = 0.f, q = 0.f;
    #pragma unroll 8
    for (int r = 0; r < 256; r++) {
        float v = xb[r * D_SZ + t];
        s += v; q += v * v;
    }
    g_colsum[g * D_SZ + t] = s;
    red[t] = q; __syncthreads();
    for (int sft = 128; sft > 0; sft >>= 1) { if (t < sft) red[t] += red[t + sft]; __syncthreads(); }
    if (t == 0) g_qpart[g] = red[0];
}

// ---------------------------------------------------------------------------
// Kernel 2: encoder GEMM via mma.sync (fp16 HMMA), 128x128x256 per block.
// K staged in 4 chunks of 64 (2 buffers); smem 74.2KB -> 2 CTAs/SM.
// K-accumulation order identical to previous rounds (acts bit-identical).
// ---------------------------------------------------------------------------
#define KC2      64
#define PITCH2   72                    // halfs per staged row (144B)
#define STG2     (128 * PITCH2 * 2)    // 18432 B per buffer
#define OFF2_A(p) ((p) * STG2)
#define OFF2_B(p) (2 * STG2 + (p) * STG2)
#define OFF2_BES (4 * STG2)            // 73728
#define ESM2_TOTAL (OFF2_BES + 512)
#define STAGE_PITCH_U32 68

__global__ __launch_bounds__(256, 2) void encode_kernel(const float* __restrict__ b_enc,
                                                        int rgBase)
{
    extern __shared__ char smem[];
    const uint32_t sbase = smem_u32(smem);
    const int t = threadIdx.x;
    const int wid = t >> 5, lane = t & 31;
    const int h0 = blockIdx.x * 128;
    const int r0 = rgBase + blockIdx.y * 128;

    const int wm = wid >> 2, wn = wid & 3;
    const int m0w = wm * 64, n0w = wn * 32;

    const char* gA = (const char*)(g_xh  + (size_t)r0 * D_SZ);
    const char* gB = (const char*)(g_weh + (size_t)h0 * D_SZ);

    // stage loader: chunk s (64 cols) into buffer parity p
    auto load_stage = [&](int s, int p) {
        #pragma unroll
        for (int i = 0; i < 4; i++) {
            int idx = t + 256 * i;             // 1024 chunks of 16B per operand
            int row = idx >> 3, q = idx & 7;
            uint32_t dOff = (uint32_t)((row * PITCH2 + q * 8) * 2);
            size_t gOff = ((size_t)row * D_SZ + s * KC2 + q * 8) * 2;
            CP_ASYNC16(sbase + OFF2_A(p) + dOff, gA + gOff);
            CP_ASYNC16(sbase + OFF2_B(p) + dOff, gB + gOff);
        }
        CP_COMMIT();
    };

    load_stage(0, 0);
    load_stage(1, 1);
    ((float*)(smem + OFF2_BES))[t & 127] = b_enc[h0 + (t & 127)];

    float acc[16][4];
    #pragma unroll
    for (int f = 0; f < 16; f++)
        #pragma unroll
        for (int e = 0; e < 4; e++) acc[f][e] = 0.f;

    const int aRow = lane & 15;
    const int aCol = (lane >> 4) << 3;
    const int bRow = ((lane >> 4) << 3) + (lane & 7);
    const int bCol = ((lane >> 3) & 1) << 3;

    CP_WAIT(1);          // stage 0 ready
    __syncthreads();

    #pragma unroll
    for (int s = 0; s < 4; s++) {
        const int p = s & 1;
        const uint32_t aBase = sbase + OFF2_A(p) + ((m0w + aRow) * PITCH2 + aCol) * 2;
        const uint32_t bBase = sbase + OFF2_B(p) + ((n0w + bRow) * PITCH2 + bCol) * 2;
        #pragma unroll
        for (int k0 = 0; k0 < KC2; k0 += 16) {
            uint32_t a[4][4], b[2][4];
            #pragma unroll
            for (int i = 0; i < 4; i++)
                ldsm_x4(a[i][0], a[i][1], a[i][2], a[i][3],
                        aBase + (i * 16 * PITCH2 + k0) * 2);
            #pragma unroll
            for (int jp = 0; jp < 2; jp++)
                ldsm_x4(b[jp][0], b[jp][1], b[jp][2], b[jp][3],
                        bBase + (jp * 16 * PITCH2 + k0) * 2);
            #pragma unroll
            for (int i = 0; i < 4; i++)
                #pragma unroll
                for (int j = 0; j < 4; j++)
                    mma_16816(acc[i * 4 + j], a[i][0], a[i][1], a[i][2], a[i][3],
                              b[j >> 1][(j & 1) * 2], b[j >> 1][(j & 1) * 2 + 1]);
        }
        if (s < 2) {
            __syncthreads();               // all warps done reading buffer p
            load_stage(s + 2, p);          // prefetch into freed buffer
            CP_WAIT(1);                    // next stage (s+1) arrived
            __syncthreads();
        } else if (s == 2) {
            CP_WAIT(0);                    // final stage arrived
            __syncthreads();
        }
    }
    __syncthreads();

    // epilogue: bias+relu -> fp16, stage (reuses A buffers), coalesced store
    uint32_t* stg = (uint32_t*)smem;
    const float* bes = (const float*)(smem + OFF2_BES);
    const int qr = lane >> 2, qc = lane & 3;
    #pragma unroll
    for (int i = 0; i < 4; i++) {
        #pragma unroll
        for (int j = 0; j < 4; j++) {
            int col = n0w + j * 8 + qc * 2;
            float b0 = bes[col], b1 = bes[col + 1];
            const float* c = acc[i * 4 + j];
            int mA = m0w + i * 16 + qr;
            float v0 = fmaxf(c[0] + b0, 0.f), v1 = fmaxf(c[1] + b1, 0.f);
            float v2 = fmaxf(c[2] + b0, 0.f), v3 = fmaxf(c[3] + b1, 0.f);
            uint32_t p0 = (uint32_t)__half_as_ushort(__float2half_rn(v0))
                        | ((uint32_t)__half_as_ushort(__float2half_rn(v1)) << 16);
            uint32_t p1 = (uint32_t)__half_as_ushort(__float2half_rn(v2))
                        | ((uint32_t)__half_as_ushort(__float2half_rn(v3)) << 16);
            stg[mA * STAGE_PITCH_U32 + (col >> 1)] = p0;
            stg[(mA + 8) * STAGE_PITCH_U32 + (col >> 1)] = p1;
        }
    }
    __syncthreads();
    #pragma unroll
    for (int i = 0; i < 8; i++) {
        int idx = t + 256 * i;
        int row = idx >> 4, q = idx & 15;
        uint4 v = *(const uint4*)((const char*)stg + row * (STAGE_PITCH_U32 * 4) + q * 16);
        *(uint4*)((char*)g_acts + ((size_t)(r0 + row) * H_SZ + h0) * 2 + q * 16) = v;
    }
}

// ---------------------------------------------------------------------------
// Kernel 3: FUSED select = threshold search + candidate collect + exact fp32
// rescore. One block per row. Search: 1 barrier/iter (double-buffered warp
// counts, replicated sum). Scores: verbatim sequential fmaf chain (R8).
// ---------------------------------------------------------------------------
__device__ __forceinline__ int cnt_ge2(const uint32_t* w, uint32_t mid,
                                       volatile int* cwb, int wid, int lane)
{
    uint32_t mm = mid | (mid << 16);
    uint32_t c2 = 0;
    #pragma unroll
    for (int i = 0; i < 16; i++)
        c2 = __vadd2(c2, __vcmpgeu2(w[i], mm) & 0x00010001u);
    unsigned local = (c2 & 0xFFFFu) + (c2 >> 16);
    unsigned r = __reduce_add_sync(0xffffffffu, local);
    if (lane == 0) cwb[wid] = (int)r;
    __syncthreads();
    int s = 0;
    #pragma unroll
    for (int i = 0; i < 8; i++) s += cwb[i];
    return s;                      // same value in all threads
}

__global__ __launch_bounds__(256) void select_kernel(
    const float* __restrict__ x, const float* __restrict__ W_enc,
    const float* __restrict__ b_enc, const float* __restrict__ b_dec,
    int rgBase)
{
    extern __shared__ float sm[];
    float* xs  = sm;                       // [256]
    float* cv  = sm + 256;                 // [CAND_MAX]
    int*   ci  = (int*)(sm + 256 + CAND_MAX);
    float* stg = sm + 256 + 2 * CAND_MAX;  // [RS_BATCH][RS_PITCH]
    __shared__ int cw[2][8];
    __shared__ int s_cnt;

    const int row = rgBase + blockIdx.x;
    const int t = threadIdx.x, wid = t >> 5, lane = t & 31;

    const uint4* arow = (const uint4*)((const char*)g_acts + (size_t)row * H_SZ * 2);
    uint4 q[4];
    #pragma unroll
    for (int i = 0; i < 4; i++) q[i] = arow[t + 256 * i];
    uint32_t* w = (uint32_t*)q;            // 32 u16 values

    xs[t] = x[(size_t)row * D_SZ + t] - b_dec[t];
    if (t == 0) s_cnt = 0;

    // windowed binary search; early-exit certifies count, skipping verify
    uint32_t lo = 0x3BFF, hi = 0x4800;
    int T = -1, buf = 0;
    bool found = false;
    for (int it = 0; it < 12 && hi - lo > 1; it++) {
        uint32_t mid = (lo + hi) >> 1;
        int c = cnt_ge2(w, mid, cw[buf], wid, lane);
        buf ^= 1;
        if (c >= CAND_K) {
            lo = mid;
            if (c <= CAND_HI) { T = (int)mid; found = true; break; }
        } else hi = mid;
    }
    if (!found) {
        T = (int)lo;
        int cF = cnt_ge2(w, (uint32_t)T, cw[buf], wid, lane);
        buf ^= 1;
        if (cF < CAND_K) {                 // bracket broke: full-range fallback
            lo = 1; hi = 0x7C00;
            while (hi - lo > 1) {
                uint32_t mid = (lo + hi) >> 1;
                int c = cnt_ge2(w, mid, cw[buf], wid, lane);
                buf ^= 1;
                if (c >= CAND_K) lo = mid; else hi = mid;
            }
            T = (int)lo;
        }
    }
    const uint32_t Tc = (T > TK_MARGIN) ? (uint32_t)(T - TK_MARGIN) : 1u;

    // collect candidate indices into smem
    #pragma unroll
    for (int i = 0; i < 16; i++) {
        int cbase = (t + 256 * (i >> 2)) * 8 + (i & 3) * 2;
        uint32_t u0 = w[i] & 0xFFFFu, u1 = w[i] >> 16;
        if (u0 >= Tc) {
            int p = atomicAdd(&s_cnt, 1);
            if (p < CAND_MAX) ci[p] = cbase;
        }
        if (u1 >= Tc) {
            int p = atomicAdd(&s_cnt, 1);
            if (p < CAND_MAX) ci[p] = cbase + 1;
        }
    }
    __syncthreads();
    const int cnt = (s_cnt < CAND_MAX) ? s_cnt : CAND_MAX;

    // rescore: batches staged coalesced, then verbatim sequential fmaf chain
    for (int b0 = 0; b0 < cnt; b0 += RS_BATCH) {
        int nb = min(RS_BATCH, cnt - b0);
        for (int j = t; j < nb * 64; j += 256) {
            int r = j >> 6, c4 = j & 63;
            int idx = ci[b0 + r];
            float4 v = __ldg((const float4*)(W_enc + (size_t)idx * D_SZ) + c4);
            *(float4*)(stg + r * RS_PITCH + c4 * 4) = v;
        }
        __syncthreads();
        if (t < nb) {
            int idx = ci[b0 + t];
            const float* wrow = stg + t * RS_PITCH;
            float s = 0.f;
            #pragma unroll 8
            for (int k = 0; k < D_SZ; k++) s = fmaf(xs[k], wrow[k], s);
            cv[b0 + t] = fmaxf(s + b_enc[idx], 0.f);
        }
        __syncthreads();
    }

    if (t < cnt) {
        float v = cv[t]; int id = ci[t];
        int rank = 0;
        for (int j = 0; j < cnt; j++) {
            float vo = cv[j];
            rank += (vo > v) || (vo == v && ci[j] < id);
        }
        if (rank < K_TOP) {
            g_tkval[row * K_TOP + rank] = v;
            g_tkidx[row * K_TOP + rank] = id;
        }
    }
}

// ---------------------------------------------------------------------------
// Kernel 4: sparse decode + counts + e^2 partials
// ---------------------------------------------------------------------------
__global__ __launch_bounds__(256) void decode_kernel(
    const float* __restrict__ x, const float* __restrict__ W_dec,
    const float* __restrict__ b_dec, float* __restrict__ out, int rgBase)
{
    __shared__ float sval[8][K_TOP];
    __shared__ int   sidx[8][K_TOP];
    __shared__ float red[256];
    int r0 = rgBase + blockIdx.x * 8, t = threadIdx.x;
    {
        int r = t >> 5, j = t & 31;
        int row = r0 + r;
        sval[r][j] = g_tkval[row * K_TOP + j];
        int id = g_tkidx[row * K_TOP + j];
        sidx[r][j] = id;
        atomicAdd(&g_counts[id], 1);
    }
    __syncthreads();
    float bd = b_dec[t];
    float esum = 0.f;
    #pragma unroll
    for (int r = 0; r < 8; r++) {
        float acc = bd;
        #pragma unroll
        for (int j = 0; j < K_TOP; j++)
            acc += sval[r][j] * __ldg(&W_dec[(size_t)sidx[r][j] * D_SZ + t]);
        int row = r0 + r;
        out[(size_t)row * D_SZ + t] = acc;
        float e = acc - x[(size_t)row * D_SZ + t];
        esum += e * e;
    }
    red[t] = esum; __syncthreads();
    for (int s = 128; s > 0; s >>= 1) { if (t < s) red[t] += red[t + s]; __syncthreads(); }
    if (t == 0) g_e2part[r0 / 8] = red[0];
}

// ---------------------------------------------------------------------------
// Kernel 5: finalize
// ---------------------------------------------------------------------------
__global__ __launch_bounds__(256) void finalize_kernel(float* __restrict__ out)
{
    __shared__ float red[256];
    __shared__ float sh_var, sh_q, sh_e2;
    int t = threadIdx.x;
    float S = 0.f;
    for (int g = 0; g < 64; g++) S += g_colsum[g * D_SZ + t];
    red[t] = S * S * (1.0f / (float)B_SZ);
    __syncthreads();
    for (int s = 128; s > 0; s >>= 1) { if (t < s) red[t] += red[t + s]; __syncthreads(); }
    if (t == 0) sh_var = red[0];
    __syncthreads();
    red[t] = (t < 64) ? g_qpart[t] : 0.f;
    __syncthreads();
    for (int s = 128; s > 0; s >>= 1) { if (t < s) red[t] += red[t + s]; __syncthreads(); }
    if (t == 0) sh_q = red[0];
    __syncthreads();
    float e2 = 0.f;
    for (int i = t; i < B_SZ / 8; i += 256) e2 += g_e2part[i];
    red[t] = e2; __syncthreads();
    for (int s = 128; s > 0; s >>= 1) { if (t < s) red[t] += red[t + s]; __syncthreads(); }
    if (t == 0) sh_e2 = red[0];
    __syncthreads();
    if (t == 0) {
        float total_var = sh_q - sh_var;
        out[(size_t)B_SZ * D_SZ + H_SZ] = sh_e2 / total_var;
    }
    for (int i = t; i < H_SZ; i += 256)
        out[(size_t)B_SZ * D_SZ + i] = (float)g_counts[i];
}

// ---------------------------------------------------------------------------
// Launch
// ---------------------------------------------------------------------------
extern "C" void kernel_launch(void* const* d_in, const int* in_sizes, int n_in,
                              void* d_out, int out_size)
{
    const float* x     = (const float*)d_in[0];
    const float* W_enc = (const float*)d_in[1];
    const float* b_enc = (const float*)d_in[2];
    const float* W_dec = (const float*)d_in[3];
    const float* b_dec = (const float*)d_in[4];
    float* out = (float*)d_out;

    cudaFuncSetAttribute(encode_kernel,
                         cudaFuncAttributeMaxDynamicSharedMemorySize, ESM2_TOTAL);
    cudaFuncSetAttribute(select_kernel,
                         cudaFuncAttributeMaxDynamicSharedMemorySize, SEL_SMEM_BYTES);

    conv_kernel<<<3072, 256>>>(x, W_enc, b_dec);
    colstat_kernel<<<64, 256>>>(x);
    for (int g = 0; g < NGRP; g++) {
        int rg = g * ROWG;
        encode_kernel<<<dim3(H_SZ / 128, ROWG / 128), 256, ESM2_TOTAL>>>(b_enc, rg);
        select_kernel<<<ROWG, 256, SEL_SMEM_BYTES>>>(x, W_enc, b_enc, b_dec, rg);
        decode_kernel<<<ROWG / 8, 256>>>(x, W_dec, b_dec, out, rg);
    }
    finalize_kernel<<<1, 256>>>(out);
}

// round 10
// speedup vs baseline: 4.1915x; 1.1893x over previous
#include <cuda_runtime.h>
#include <cuda_fp16.h>
#include <cstdint>

#define B_SZ   16384
#define D_SZ   256
#define H_SZ   8192
#define K_TOP  32
#define CAND_K   36     // min acceptable candidate count at threshold
#define CAND_HI  56     // max acceptable count at threshold (early-exit window)
#define CAND_MAX 96     // candidate buffer cap
#define TK_MARGIN 4     // ulp margin below threshold
#define ROWG   4096     // row-group size (acts slab 64MB -> L2 resident)
#define NGRP   (B_SZ / ROWG)

// select (fused topk+rescore) staging — 24-row batches keep smem at 26.1KB
// so 8 CTAs/SM are resident (occupancy was the R9 bottleneck).
#define RS_BATCH 24
#define RS_PITCH 260    // words per staged row (1040B: 16B-aligned, bank-skewed)
#define SEL_SMEM_FLOATS (256 + CAND_MAX + CAND_MAX + RS_BATCH * RS_PITCH)
#define SEL_SMEM_BYTES  (SEL_SMEM_FLOATS * 4)

// ---------------------------------------------------------------------------
// Scratch (__device__ globals)
// ---------------------------------------------------------------------------
__device__ __half g_xh [B_SZ * D_SZ];                 // fp16(x - b_dec)
__device__ __half g_weh[H_SZ * D_SZ];                 // fp16(W_enc)
__device__ __half g_acts[(size_t)B_SZ * H_SZ];        // fp16 relu(pre_acts)
__device__ float g_tkval[B_SZ * K_TOP];
__device__ int   g_tkidx[B_SZ * K_TOP];
__device__ int   g_counts[H_SZ];
__device__ float g_colsum[64 * D_SZ];
__device__ float g_qpart[64];
__device__ float g_e2part[B_SZ / 8];

// ---------------------------------------------------------------------------
// Helpers
// ---------------------------------------------------------------------------
__device__ __forceinline__ uint32_t smem_u32(const void* p) {
    uint32_t a;
    asm("{ .reg .u64 t; cvta.to.shared.u64 t, %1; cvt.u32.u64 %0, t; }" : "=r"(a) : "l"(p));
    return a;
}
#define CP_ASYNC16(dst, src) \
    asm volatile("cp.async.cg.shared.global [%0], [%1], 16;" :: "r"(dst), "l"(src))
#define CP_COMMIT() asm volatile("cp.async.commit_group;")
#define CP_WAIT(n)  asm volatile("cp.async.wait_group %0;" :: "n"(n))

__device__ __forceinline__ void ldsm_x4(uint32_t& r0, uint32_t& r1, uint32_t& r2, uint32_t& r3,
                                        uint32_t addr) {
    asm volatile("ldmatrix.sync.aligned.m8n8.x4.shared.b16 {%0,%1,%2,%3}, [%4];"
                 : "=r"(r0), "=r"(r1), "=r"(r2), "=r"(r3) : "r"(addr));
}
__device__ __forceinline__ void mma_16816(float* c, uint32_t a0, uint32_t a1, uint32_t a2,
                                          uint32_t a3, uint32_t b0, uint32_t b1) {
    asm volatile(
        "mma.sync.aligned.m16n8k16.row.col.f32.f16.f16.f32 "
        "{%0,%1,%2,%3}, {%4,%5,%6,%7}, {%8,%9}, {%0,%1,%2,%3};"
        : "+f"(c[0]), "+f"(c[1]), "+f"(c[2]), "+f"(c[3])
        : "r"(a0), "r"(a1), "r"(a2), "r"(a3), "r"(b0), "r"(b1));
}

// ---------------------------------------------------------------------------
// Kernel 0: convert x -> fp16(x - b_dec), W_enc -> fp16
// ---------------------------------------------------------------------------
__global__ __launch_bounds__(256) void conv_kernel(
    const float* __restrict__ x, const float* __restrict__ W_enc,
    const float* __restrict__ b_dec)
{
    int b = blockIdx.x, t = threadIdx.x;
    if (b < 2048) {
        size_t e0 = ((size_t)b * 256 + t) * 8;
        int col = (int)(e0 & (D_SZ - 1));
        float4 v0 = *(const float4*)(x + e0);
        float4 v1 = *(const float4*)(x + e0 + 4);
        float4 d0 = *(const float4*)(b_dec + col);
        float4 d1 = *(const float4*)(b_dec + col + 4);
        __half o[8];
        o[0]=__float2half_rn(v0.x-d0.x); o[1]=__float2half_rn(v0.y-d0.y);
        o[2]=__float2half_rn(v0.z-d0.z); o[3]=__float2half_rn(v0.w-d0.w);
        o[4]=__float2half_rn(v1.x-d1.x); o[5]=__float2half_rn(v1.y-d1.y);
        o[6]=__float2half_rn(v1.z-d1.z); o[7]=__float2half_rn(v1.w-d1.w);
        *(uint4*)(g_xh + e0) = *(uint4*)o;
    } else {
        size_t e0 = ((size_t)(b - 2048) * 256 + t) * 8;
        float4 v0 = *(const float4*)(W_enc + e0);
        float4 v1 = *(const float4*)(W_enc + e0 + 4);
        __half o[8];
        o[0]=__float2half_rn(v0.x); o[1]=__float2half_rn(v0.y);
        o[2]=__float2half_rn(v0.z); o[3]=__float2half_rn(v0.w);
        o[4]=__float2half_rn(v1.x); o[5]=__float2half_rn(v1.y);
        o[6]=__float2half_rn(v1.z); o[7]=__float2half_rn(v1.w);
        *(uint4*)(g_weh + e0) = *(uint4*)o;
    }
}

// ---------------------------------------------------------------------------
// Kernel 1: column stats of x + zero counts
// ---------------------------------------------------------------------------
__global__ __launch_bounds__(256) void colstat_kernel(const float* __restrict__ x)
{
    __shared__ float red[256];
    int g = blockIdx.x, t = threadIdx.x;
    int gid = g * 256 + t;
    if (gid < H_SZ) g_counts[gid] = 0;
    const float* xb = x + (size_t)(g * 256) * D_SZ;
    float s = 0.f, q = 0.f;
    #pragma unroll 8
    for (int r = 0; r < 256; r++) {
        float v = xb[r * D_SZ + t];
        s += v; q += v * v;
    }
    g_colsum[g * D_SZ + t] = s;
    red[t] = q; __syncthreads();
    for (int sft = 128; sft > 0; sft >>= 1) { if (t < sft) red[t] += red[t + sft]; __syncthreads(); }
    if (t == 0) g_qpart[g] = red[0];
}

// ---------------------------------------------------------------------------
// Kernel 2: encoder GEMM via mma.sync (fp16 HMMA), 128x128x256 per block.
// K staged in 4 chunks of 64 (2 buffers); smem 74.2KB -> 2 CTAs/SM.
// ---------------------------------------------------------------------------
#define KC2      64
#define PITCH2   72
#define STG2     (128 * PITCH2 * 2)
#define OFF2_A(p) ((p) * STG2)
#define OFF2_B(p) (2 * STG2 + (p) * STG2)
#define OFF2_BES (4 * STG2)
#define ESM2_TOTAL (OFF2_BES + 512)
#define STAGE_PITCH_U32 68

__global__ __launch_bounds__(256, 2) void encode_kernel(const float* __restrict__ b_enc,
                                                        int rgBase)
{
    extern __shared__ char smem[];
    const uint32_t sbase = smem_u32(smem);
    const int t = threadIdx.x;
    const int wid = t >> 5, lane = t & 31;
    const int h0 = blockIdx.x * 128;
    const int r0 = rgBase + blockIdx.y * 128;

    const int wm = wid >> 2, wn = wid & 3;
    const int m0w = wm * 64, n0w = wn * 32;

    const char* gA = (const char*)(g_xh  + (size_t)r0 * D_SZ);
    const char* gB = (const char*)(g_weh + (size_t)h0 * D_SZ);

    auto load_stage = [&](int s, int p) {
        #pragma unroll
        for (int i = 0; i < 4; i++) {
            int idx = t + 256 * i;
            int row = idx >> 3, q = idx & 7;
            uint32_t dOff = (uint32_t)((row * PITCH2 + q * 8) * 2);
            size_t gOff = ((size_t)row * D_SZ + s * KC2 + q * 8) * 2;
            CP_ASYNC16(sbase + OFF2_A(p) + dOff, gA + gOff);
            CP_ASYNC16(sbase + OFF2_B(p) + dOff, gB + gOff);
        }
        CP_COMMIT();
    };

    load_stage(0, 0);
    load_stage(1, 1);
    ((float*)(smem + OFF2_BES))[t & 127] = b_enc[h0 + (t & 127)];

    float acc[16][4];
    #pragma unroll
    for (int f = 0; f < 16; f++)
        #pragma unroll
        for (int e = 0; e < 4; e++) acc[f][e] = 0.f;

    const int aRow = lane & 15;
    const int aCol = (lane >> 4) << 3;
    const int bRow = ((lane >> 4) << 3) + (lane & 7);
    const int bCol = ((lane >> 3) & 1) << 3;

    CP_WAIT(1);
    __syncthreads();

    #pragma unroll
    for (int s = 0; s < 4; s++) {
        const int p = s & 1;
        const uint32_t aBase = sbase + OFF2_A(p) + ((m0w + aRow) * PITCH2 + aCol) * 2;
        const uint32_t bBase = sbase + OFF2_B(p) + ((n0w + bRow) * PITCH2 + bCol) * 2;
        #pragma unroll
        for (int k0 = 0; k0 < KC2; k0 += 16) {
            uint32_t a[4][4], b[2][4];
            #pragma unroll
            for (int i = 0; i < 4; i++)
                ldsm_x4(a[i][0], a[i][1], a[i][2], a[i][3],
                        aBase + (i * 16 * PITCH2 + k0) * 2);
            #pragma unroll
            for (int jp = 0; jp < 2; jp++)
                ldsm_x4(b[jp][0], b[jp][1], b[jp][2], b[jp][3],
                        bBase + (jp * 16 * PITCH2 + k0) * 2);
            #pragma unroll
            for (int i = 0; i < 4; i++)
                #pragma unroll
                for (int j = 0; j < 4; j++)
                    mma_16816(acc[i * 4 + j], a[i][0], a[i][1], a[i][2], a[i][3],
                              b[j >> 1][(j & 1) * 2], b[j >> 1][(j & 1) * 2 + 1]);
        }
        if (s < 2) {
            __syncthreads();
            load_stage(s + 2, p);
            CP_WAIT(1);
            __syncthreads();
        } else if (s == 2) {
            CP_WAIT(0);
            __syncthreads();
        }
    }
    __syncthreads();

    uint32_t* stg = (uint32_t*)smem;
    const float* bes = (const float*)(smem + OFF2_BES);
    const int qr = lane >> 2, qc = lane & 3;
    #pragma unroll
    for (int i = 0; i < 4; i++) {
        #pragma unroll
        for (int j = 0; j < 4; j++) {
            int col = n0w + j * 8 + qc * 2;
            float b0 = bes[col], b1 = bes[col + 1];
            const float* c = acc[i * 4 + j];
            int mA = m0w + i * 16 + qr;
            float v0 = fmaxf(c[0] + b0, 0.f), v1 = fmaxf(c[1] + b1, 0.f);
            float v2 = fmaxf(c[2] + b0, 0.f), v3 = fmaxf(c[3] + b1, 0.f);
            uint32_t p0 = (uint32_t)__half_as_ushort(__float2half_rn(v0))
                        | ((uint32_t)__half_as_ushort(__float2half_rn(v1)) << 16);
            uint32_t p1 = (uint32_t)__half_as_ushort(__float2half_rn(v2))
                        | ((uint32_t)__half_as_ushort(__float2half_rn(v3)) << 16);
            stg[mA * STAGE_PITCH_U32 + (col >> 1)] = p0;
            stg[(mA + 8) * STAGE_PITCH_U32 + (col >> 1)] = p1;
        }
    }
    __syncthreads();
    #pragma unroll
    for (int i = 0; i < 8; i++) {
        int idx = t + 256 * i;
        int row = idx >> 4, q = idx & 15;
        uint4 v = *(const uint4*)((const char*)stg + row * (STAGE_PITCH_U32 * 4) + q * 16);
        *(uint4*)((char*)g_acts + ((size_t)(r0 + row) * H_SZ + h0) * 2 + q * 16) = v;
    }
}

// ---------------------------------------------------------------------------
// Kernel 3: FUSED select = threshold search + candidate collect + exact fp32
// rescore. One block per row, 8 CTAs/SM. Scores: verbatim sequential fmaf.
// ---------------------------------------------------------------------------
__device__ __forceinline__ int cnt_ge2(const uint32_t* w, uint32_t mid,
                                       volatile int* cwb, int wid, int lane)
{
    uint32_t mm = mid | (mid << 16);
    uint32_t c2 = 0;
    #pragma unroll
    for (int i = 0; i < 16; i++)
        c2 = __vadd2(c2, __vcmpgeu2(w[i], mm) & 0x00010001u);
    unsigned local = (c2 & 0xFFFFu) + (c2 >> 16);
    unsigned r = __reduce_add_sync(0xffffffffu, local);
    if (lane == 0) cwb[wid] = (int)r;
    __syncthreads();
    int s = 0;
    #pragma unroll
    for (int i = 0; i < 8; i++) s += cwb[i];
    return s;
}

__global__ __launch_bounds__(256) void select_kernel(
    const float* __restrict__ x, const float* __restrict__ W_enc,
    const float* __restrict__ b_enc, const float* __restrict__ b_dec,
    int rgBase)
{
    extern __shared__ float sm[];
    float* xs  = sm;                       // [256]
    float* cv  = sm + 256;                 // [CAND_MAX]
    int*   ci  = (int*)(sm + 256 + CAND_MAX);
    float* stg = sm + 256 + 2 * CAND_MAX;  // [RS_BATCH][RS_PITCH]
    __shared__ int cw[2][8];
    __shared__ int s_cnt;

    const int row = rgBase + blockIdx.x;
    const int t = threadIdx.x, wid = t >> 5, lane = t & 31;

    const uint4* arow = (const uint4*)((const char*)g_acts + (size_t)row * H_SZ * 2);
    uint4 q[4];
    #pragma unroll
    for (int i = 0; i < 4; i++) q[i] = arow[t + 256 * i];
    uint32_t* w = (uint32_t*)q;            // 32 u16 values

    xs[t] = x[(size_t)row * D_SZ + t] - b_dec[t];
    if (t == 0) s_cnt = 0;

    // windowed binary search; early-exit certifies count, skipping verify
    uint32_t lo = 0x3BFF, hi = 0x4800;
    int T = -1, buf = 0;
    bool found = false;
    for (int it = 0; it < 12 && hi - lo > 1; it++) {
        uint32_t mid = (lo + hi) >> 1;
        int c = cnt_ge2(w, mid, cw[buf], wid, lane);
        buf ^= 1;
        if (c >= CAND_K) {
            lo = mid;
            if (c <= CAND_HI) { T = (int)mid; found = true; break; }
        } else hi = mid;
    }
    if (!found) {
        T = (int)lo;
        int cF = cnt_ge2(w, (uint32_t)T, cw[buf], wid, lane);
        buf ^= 1;
        if (cF < CAND_K) {                 // bracket broke: full-range fallback
            lo = 1; hi = 0x7C00;
            while (hi - lo > 1) {
                uint32_t mid = (lo + hi) >> 1;
                int c = cnt_ge2(w, mid, cw[buf], wid, lane);
                buf ^= 1;
                if (c >= CAND_K) lo = mid; else hi = mid;
            }
            T = (int)lo;
        }
    }
    const uint32_t Tc = (T > TK_MARGIN) ? (uint32_t)(T - TK_MARGIN) : 1u;

    // collect candidate indices into smem
    #pragma unroll
    for (int i = 0; i < 16; i++) {
        int cbase = (t + 256 * (i >> 2)) * 8 + (i & 3) * 2;
        uint32_t u0 = w[i] & 0xFFFFu, u1 = w[i] >> 16;
        if (u0 >= Tc) {
            int p = atomicAdd(&s_cnt, 1);
            if (p < CAND_MAX) ci[p] = cbase;
        }
        if (u1 >= Tc) {
            int p = atomicAdd(&s_cnt, 1);
            if (p < CAND_MAX) ci[p] = cbase + 1;
        }
    }
    __syncthreads();
    const int cnt = (s_cnt < CAND_MAX) ? s_cnt : CAND_MAX;

    // rescore: batches staged coalesced, then verbatim sequential fmaf chain
    for (int b0 = 0; b0 < cnt; b0 += RS_BATCH) {
        int nb = min(RS_BATCH, cnt - b0);
        for (int j = t; j < nb * 64; j += 256) {
            int r = j >> 6, c4 = j & 63;
            int idx = ci[b0 + r];
            float4 v = __ldg((const float4*)(W_enc + (size_t)idx * D_SZ) + c4);
            *(float4*)(stg + r * RS_PITCH + c4 * 4) = v;
        }
        __syncthreads();
        if (t < nb) {
            int idx = ci[b0 + t];
            const float* wrow = stg + t * RS_PITCH;
            float s = 0.f;
            #pragma unroll 8
            for (int k = 0; k < D_SZ; k++) s = fmaf(xs[k], wrow[k], s);
            cv[b0 + t] = fmaxf(s + b_enc[idx], 0.f);
        }
        __syncthreads();
    }

    if (t < cnt) {
        float v = cv[t]; int id = ci[t];
        int rank = 0;
        for (int j = 0; j < cnt; j++) {
            float vo = cv[j];
            rank += (vo > v) || (vo == v && ci[j] < id);
        }
        if (rank < K_TOP) {
            g_tkval[row * K_TOP + rank] = v;
            g_tkidx[row * K_TOP + rank] = id;
        }
    }
}

// ---------------------------------------------------------------------------
// Kernel 4: sparse decode + counts + e^2 partials
// ---------------------------------------------------------------------------
__global__ __launch_bounds__(256) void decode_kernel(
    const float* __restrict__ x, const float* __restrict__ W_dec,
    const float* __restrict__ b_dec, float* __restrict__ out, int rgBase)
{
    __shared__ float sval[8][K_TOP];
    __shared__ int   sidx[8][K_TOP];
    __shared__ float red[256];
    int r0 = rgBase + blockIdx.x * 8, t = threadIdx.x;
    {
        int r = t >> 5, j = t & 31;
        int row = r0 + r;
        sval[r][j] = g_tkval[row * K_TOP + j];
        int id = g_tkidx[row * K_TOP + j];
        sidx[r][j] = id;
        atomicAdd(&g_counts[id], 1);
    }
    __syncthreads();
    float bd = b_dec[t];
    float esum = 0.f;
    #pragma unroll
    for (int r = 0; r < 8; r++) {
        float acc = bd;
        #pragma unroll
        for (int j = 0; j < K_TOP; j++)
            acc += sval[r][j] * __ldg(&W_dec[(size_t)sidx[r][j] * D_SZ + t]);
        int row = r0 + r;
        out[(size_t)row * D_SZ + t] = acc;
        float e = acc - x[(size_t)row * D_SZ + t];
        esum += e * e;
    }
    red[t] = esum; __syncthreads();
    for (int s = 128; s > 0; s >>= 1) { if (t < s) red[t] += red[t + s]; __syncthreads(); }
    if (t == 0) g_e2part[r0 / 8] = red[0];
}

// ---------------------------------------------------------------------------
// Kernel 5: finalize
// ---------------------------------------------------------------------------
__global__ __launch_bounds__(256) void finalize_kernel(float* __restrict__ out)
{
    __shared__ float red[256];
    __shared__ float sh_var, sh_q, sh_e2;
    int t = threadIdx.x;
    float S = 0.f;
    for (int g = 0; g < 64; g++) S += g_colsum[g * D_SZ + t];
    red[t] = S * S * (1.0f / (float)B_SZ);
    __syncthreads();
    for (int s = 128; s > 0; s >>= 1) { if (t < s) red[t] += red[t + s]; __syncthreads(); }
    if (t == 0) sh_var = red[0];
    __syncthreads();
    red[t] = (t < 64) ? g_qpart[t] : 0.f;
    __syncthreads();
    for (int s = 128; s > 0; s >>= 1) { if (t < s) red[t] += red[t + s]; __syncthreads(); }
    if (t == 0) sh_q = red[0];
    __syncthreads();
    float e2 = 0.f;
    for (int i = t; i < B_SZ / 8; i += 256) e2 += g_e2part[i];
    red[t] = e2; __syncthreads();
    for (int s = 128; s > 0; s >>= 1) { if (t < s) red[t] += red[t + s]; __syncthreads(); }
    if (t == 0) sh_e2 = red[0];
    __syncthreads();
    if (t == 0) {
        float total_var = sh_q - sh_var;
        out[(size_t)B_SZ * D_SZ + H_SZ] = sh_e2 / total_var;
    }
    for (int i = t; i < H_SZ; i += 256)
        out[(size_t)B_SZ * D_SZ + i] = (float)g_counts[i];
}

// ---------------------------------------------------------------------------
// Launch
// ---------------------------------------------------------------------------
extern "C" void kernel_launch(void* const* d_in, const int* in_sizes, int n_in,
                              void* d_out, int out_size)
{
    const float* x     = (const float*)d_in[0];
    const float* W_enc = (const float*)d_in[1];
    const float* b_enc = (const float*)d_in[2];
    const float* W_dec = (const float*)d_in[3];
    const float* b_dec = (const float*)d_in[4];
    float* out = (float*)d_out;

    cudaFuncSetAttribute(encode_kernel,
                         cudaFuncAttributeMaxDynamicSharedMemorySize, ESM2_TOTAL);
    cudaFuncSetAttribute(select_kernel,
                         cudaFuncAttributeMaxDynamicSharedMemorySize, SEL_SMEM_BYTES);

    conv_kernel<<<3072, 256>>>(x, W_enc, b_dec);
    colstat_kernel<<<64, 256>>>(x);
    for (int g = 0; g < NGRP; g++) {
        int rg = g * ROWG;
        encode_kernel<<<dim3(H_SZ / 128, ROWG / 128), 256, ESM2_TOTAL>>>(b_enc, rg);
        select_kernel<<<ROWG, 256, SEL_SMEM_BYTES>>>(x, W_enc, b_enc, b_dec, rg);
        decode_kernel<<<ROWG / 8, 256>>>(x, W_dec, b_dec, out, rg);
    }
    finalize_kernel<<<1, 256>>>(out);
}